// round 5
// baseline (speedup 1.0000x reference)
#include <cuda_runtime.h>
#include <math.h>
#include <stdint.h>

// Problem constants
#define D_MODEL 512
#define HDIM    2048
#define TSEQ    4096
#define NB      2
#define NTOK    (NB * TSEQ)  // 8192

#define STAGE_FLOATS 9216                    // A(128*36=4608) + B(<=4608) per stage
#define NSTAGE 3
#define SMEM_BYTES   (NSTAGE * STAGE_FLOATS * 4)  // 110592

// -------- static scratch (allocation-free per harness rules) --------
__device__ float g_q[(size_t)NTOK * D_MODEL];
__device__ float g_k[(size_t)NTOK * D_MODEL];
__device__ float g_v[(size_t)NTOK * D_MODEL];
__device__ float g_attn[(size_t)NTOK * D_MODEL];
__device__ float g_x[(size_t)NTOK * D_MODEL];
__device__ float g_y[(size_t)NTOK * D_MODEL];
__device__ float g_h[(size_t)NTOK * HDIM];
__device__ float g_s[(size_t)NB * TSEQ * TSEQ];
// tf32-pre-rounded copies of raw inputs
__device__ float g_tokr[(size_t)NTOK * D_MODEL];
__device__ float g_wq[(size_t)D_MODEL * D_MODEL];
__device__ float g_wk[(size_t)D_MODEL * D_MODEL];
__device__ float g_wv[(size_t)D_MODEL * D_MODEL];
__device__ float g_w1[(size_t)D_MODEL * HDIM];
__device__ float g_w2[(size_t)HDIM * D_MODEL];

// ---------------------------------------------------------------------------
// helpers
// ---------------------------------------------------------------------------
__device__ __forceinline__ float to_tf32(float x) {
    uint32_t u;
    asm("cvt.rna.tf32.f32 %0, %1;" : "=r"(u) : "f"(x));
    return __uint_as_float(u);
}

__device__ __forceinline__ void mma_tf32(float c[4], const float a[4], const float b[2]) {
    asm volatile(
        "mma.sync.aligned.m16n8k8.row.col.f32.tf32.tf32.f32 "
        "{%0,%1,%2,%3}, {%4,%5,%6,%7}, {%8,%9}, {%0,%1,%2,%3};"
        : "+f"(c[0]), "+f"(c[1]), "+f"(c[2]), "+f"(c[3])
        : "r"(__float_as_uint(a[0])), "r"(__float_as_uint(a[1])),
          "r"(__float_as_uint(a[2])), "r"(__float_as_uint(a[3])),
          "r"(__float_as_uint(b[0])), "r"(__float_as_uint(b[1])));
}

__device__ __forceinline__ uint32_t smem_u32(const void* p) {
    return (uint32_t)__cvta_generic_to_shared(p);
}
__device__ __forceinline__ void cp16(uint32_t d, const void* s) {
    asm volatile("cp.async.cg.shared.global [%0], [%1], 16;" :: "r"(d), "l"(s));
}
__device__ __forceinline__ void cp_commit() {
    asm volatile("cp.async.commit_group;");
}
template <int N>
__device__ __forceinline__ void cp_wait() {
    asm volatile("cp.async.wait_group %0;" :: "n"(N));
}

// ============================================================================
// tf32 tensor-core GEMM body, cp.async 3-stage pipeline, prefetch depth 2,
// load-issue BEFORE compute, one barrier per k-iter.
// All inputs must already be tf32-representable (HMMA truncation lossless).
// Block 128x128, BK=32, 256 threads, 8 warps of 64x32 (m16n8k8).
//   TRANSB=0: B is KxN; smem [k][n] stride 136.  TRANSB=1: B is NxK; [n][k] s36.
//   KLIMIT=1: K clamped to (blockIdx.y+1)*128 (causal P@V).
//   ROUND_OUT=1: epilogue rounds output to tf32 (rna).
// ============================================================================
template <int RELU, int KLIMIT, int TRANSB, int ROUND_OUT>
__device__ __forceinline__ void gemm_body(
    const float* __restrict__ A, const float* __restrict__ B,
    const float* __restrict__ bias, float* __restrict__ C,
    int M, int N, int K)
{
    extern __shared__ float smem[];
    const int tid = threadIdx.x;
    const int m0 = blockIdx.y * 128;
    const int n0 = blockIdx.x * 128;
    const int Keff = KLIMIT ? min(K, ((int)blockIdx.y + 1) * 128) : K;
    const int NUMK = Keff >> 5;  // always >= 4 here

    const int lane = tid & 31;
    const int gid  = lane >> 2;
    const int tg   = lane & 3;
    const int warp = tid >> 5;
    const int mw   = (warp >> 2) * 64;
    const int nw   = (warp & 3) * 32;

    auto load_stage = [&](int s) {
        float* As = smem + (s % NSTAGE) * STAGE_FLOATS;
        float* Bs = As + 4608;
        const int kt = s << 5;
#pragma unroll
        for (int i = 0; i < 4; i++) {
            int idx = tid + i * 256;
            int row = idx >> 3;
            int c4  = (idx & 7) << 2;
            cp16(smem_u32(As + row * 36 + c4), A + (size_t)(m0 + row) * K + kt + c4);
            if (TRANSB) {
                cp16(smem_u32(Bs + row * 36 + c4), B + (size_t)(n0 + row) * K + kt + c4);
            } else {
                int kr = idx >> 5;
                int nc = (idx & 31) << 2;
                cp16(smem_u32(Bs + kr * 136 + nc), B + (size_t)(kt + kr) * N + n0 + nc);
            }
        }
    };

    float acc[4][4][4] = {};

    load_stage(0); cp_commit();
    load_stage(1); cp_commit();

    for (int k = 0; k < NUMK; k++) {
        cp_wait<1>();        // stage k resident
        __syncthreads();     // visibility + all warps done with stage k-1's slot
        if (k + 2 < NUMK) load_stage(k + 2);  // into slot (k-1)%3: safe post-barrier
        cp_commit();

        const float* As = smem + (k % NSTAGE) * STAGE_FLOATS;
        const float* Bs = As + 4608;

#pragma unroll
        for (int ks = 0; ks < 4; ks++) {
            const int kk = ks * 8;
            float a[4][4];
#pragma unroll
            for (int i = 0; i < 4; i++) {
                int mb = (mw + i * 16 + gid) * 36;
                a[i][0] = As[mb + kk + tg];
                a[i][1] = As[mb + 8 * 36 + kk + tg];
                a[i][2] = As[mb + kk + tg + 4];
                a[i][3] = As[mb + 8 * 36 + kk + tg + 4];
            }
            float b[4][2];
#pragma unroll
            for (int j = 0; j < 4; j++) {
                if (TRANSB) {
                    int nb = (nw + j * 8 + gid) * 36;
                    b[j][0] = Bs[nb + kk + tg];
                    b[j][1] = Bs[nb + kk + tg + 4];
                } else {
                    b[j][0] = Bs[(kk + tg) * 136 + nw + j * 8 + gid];
                    b[j][1] = Bs[(kk + tg + 4) * 136 + nw + j * 8 + gid];
                }
            }
#pragma unroll
            for (int i = 0; i < 4; i++)
#pragma unroll
                for (int j = 0; j < 4; j++) mma_tf32(acc[i][j], a[i], b[j]);
        }
    }

#pragma unroll
    for (int i = 0; i < 4; i++) {
        int m = m0 + mw + i * 16 + gid;
#pragma unroll
        for (int j = 0; j < 4; j++) {
            int n = n0 + nw + j * 8 + tg * 2;
            float2 lo = make_float2(acc[i][j][0], acc[i][j][1]);
            float2 hi = make_float2(acc[i][j][2], acc[i][j][3]);
            if (bias) {
                float b0 = bias[n], b1 = bias[n + 1];
                lo.x += b0; lo.y += b1; hi.x += b0; hi.y += b1;
            }
            if (RELU) {
                lo.x = fmaxf(lo.x, 0.f); lo.y = fmaxf(lo.y, 0.f);
                hi.x = fmaxf(hi.x, 0.f); hi.y = fmaxf(hi.y, 0.f);
            }
            if (ROUND_OUT) {
                lo.x = to_tf32(lo.x); lo.y = to_tf32(lo.y);
                hi.x = to_tf32(hi.x); hi.y = to_tf32(hi.y);
            }
            *(float2*)(C + (size_t)m * N + n) = lo;
            *(float2*)(C + (size_t)(m + 8) * N + n) = hi;
        }
    }
}

template <int RELU, int KLIMIT, int TRANSB, int ROUND_OUT>
__global__ __launch_bounds__(256, 2) void gemm_tc(
    const float* __restrict__ Aall, const float* __restrict__ Ball,
    const float* __restrict__ bias, float* __restrict__ Call,
    int M, int N, int K, long sA, long sB, long sC)
{
    if (TRANSB && blockIdx.x > blockIdx.y) return;  // fully-masked score tile
    gemm_body<RELU, KLIMIT, TRANSB, ROUND_OUT>(
        Aall + (size_t)blockIdx.z * sA, Ball + (size_t)blockIdx.z * sB,
        bias, Call + (size_t)blockIdx.z * sC, M, N, K);
}

// Fused QKV: one launch, blockIdx.z selects projection.
__global__ __launch_bounds__(256, 2) void qkv_kernel(
    const float* __restrict__ tok,
    const float* __restrict__ Wq, const float* __restrict__ Wk, const float* __restrict__ Wv,
    const float* __restrict__ bq, const float* __restrict__ bk, const float* __restrict__ bv,
    float* __restrict__ q, float* __restrict__ k, float* __restrict__ v)
{
    const float* W = blockIdx.z == 0 ? Wq : (blockIdx.z == 1 ? Wk : Wv);
    const float* b = blockIdx.z == 0 ? bq : (blockIdx.z == 1 ? bk : bv);
    float*       C = blockIdx.z == 0 ? q  : (blockIdx.z == 1 ? k  : v);
    gemm_body<0, 0, 0, 1>(tok, W, b, C, NTOK, D_MODEL, D_MODEL);
}

// Pre-round raw inputs to tf32 (rna), vectorized.
__global__ __launch_bounds__(256) void round_kernel(
    const float* __restrict__ in, float* __restrict__ out, int n4)
{
    int i = blockIdx.x * 256 + threadIdx.x;
    if (i < n4) {
        float4 v = ((const float4*)in)[i];
        v.x = to_tf32(v.x); v.y = to_tf32(v.y);
        v.z = to_tf32(v.z); v.w = to_tf32(v.w);
        ((float4*)out)[i] = v;
    }
}

// ---------------------------------------------------------------------------
// FMA-only exp (input <= 0 after max-subtract; clamped).
// ---------------------------------------------------------------------------
__device__ __forceinline__ float fast_exp(float x) {
    x = fmaxf(x, -87.0f);
    float z = x * 1.4426950408889634f;
    float n = rintf(z);
    float t = z - n;
    float p = 1.5403530e-4f;
    p = fmaf(p, t, 1.3333558e-3f);
    p = fmaf(p, t, 9.6181291e-3f);
    p = fmaf(p, t, 5.5504109e-2f);
    p = fmaf(p, t, 2.4022651e-1f);
    p = fmaf(p, t, 6.9314718e-1f);
    p = fmaf(p, t, 1.0f);
    int e = (int)n;
    return p * __int_as_float((e + 127) << 23);
}

// ============================================================================
// Row softmax (in-place, register-resident). Output rounded to tf32 so the
// PV GEMM's cp.async truncation is lossless. Zeros written up to next 128.
// ============================================================================
__global__ __launch_bounds__(256) void softmax_kernel(
    float* __restrict__ S, const float* __restrict__ ds_ptr)
{
    __shared__ float red[8];

    const int t = blockIdx.x;
    const int b = blockIdx.y;
    const int tid = threadIdx.x;
    const int lane = tid & 31;
    const int wid  = tid >> 5;
    float* row = S + ((size_t)b * TSEQ + t) * TSEQ;

    const float ds = *ds_ptr;
    const float scale = rsqrtf((float)D_MODEL);
    const int len = t + 1;
    const int limit = ((t >> 7) + 1) << 7;

    float v[16];
    float mx = -1e30f;
#pragma unroll
    for (int it = 0; it < 16; it++) {
        int s = tid + it * 256;
        float val = -1e30f;
        if (s < len) val = (row[s] - ds * (float)(t - s)) * scale;
        v[it] = val;
        mx = fmaxf(mx, val);
    }
#pragma unroll
    for (int o = 16; o; o >>= 1) mx = fmaxf(mx, __shfl_xor_sync(0xffffffffu, mx, o));
    if (lane == 0) red[wid] = mx;
    __syncthreads();
    float mall = -1e30f;
#pragma unroll
    for (int w = 0; w < 8; w++) mall = fmaxf(mall, red[w]);
    __syncthreads();

    float sum = 0.f;
#pragma unroll
    for (int it = 0; it < 16; it++) {
        int s = tid + it * 256;
        float e = (s < len) ? fast_exp(v[it] - mall) : 0.f;
        v[it] = e;
        sum += e;
    }
#pragma unroll
    for (int o = 16; o; o >>= 1) sum += __shfl_xor_sync(0xffffffffu, sum, o);
    if (lane == 0) red[wid] = sum;
    __syncthreads();
    float sall = 0.f;
#pragma unroll
    for (int w = 0; w < 8; w++) sall += red[w];
    const float inv = 1.0f / sall;

#pragma unroll
    for (int it = 0; it < 16; it++) {
        int s = tid + it * 256;
        if (s < len)        row[s] = to_tf32(v[it] * inv);
        else if (s < limit) row[s] = 0.f;
    }
}

// ============================================================================
// LayerNorm over last dim (512): out = LN(A + R) * gamma + beta.
// ROUND=1 rounds the output to tf32 (feeds a GEMM).
// ============================================================================
template <int ROUND>
__global__ __launch_bounds__(128) void ln_kernel(
    const float* __restrict__ A, const float* __restrict__ R,
    const float* __restrict__ gamma, const float* __restrict__ beta,
    float* __restrict__ out)
{
    __shared__ float sh[4];
    const int row = blockIdx.x;
    const int tid = threadIdx.x;
    const size_t base = (size_t)row * D_MODEL + tid * 4;

    float4 a = *(const float4*)(A + base);
    float4 r = *(const float4*)(R + base);
    float x0 = a.x + r.x, x1 = a.y + r.y, x2 = a.z + r.z, x3 = a.w + r.w;

    float s = x0 + x1 + x2 + x3;
    for (int o = 16; o; o >>= 1) s += __shfl_xor_sync(0xffffffffu, s, o);
    if ((tid & 31) == 0) sh[tid >> 5] = s;
    __syncthreads();
    const float mean = (sh[0] + sh[1] + sh[2] + sh[3]) * (1.0f / D_MODEL);
    __syncthreads();

    float d0 = x0 - mean, d1 = x1 - mean, d2 = x2 - mean, d3 = x3 - mean;
    float sq = d0 * d0 + d1 * d1 + d2 * d2 + d3 * d3;
    for (int o = 16; o; o >>= 1) sq += __shfl_xor_sync(0xffffffffu, sq, o);
    if ((tid & 31) == 0) sh[tid >> 5] = sq;
    __syncthreads();
    const float var = (sh[0] + sh[1] + sh[2] + sh[3]) * (1.0f / D_MODEL);
    const float rstd = rsqrtf(var + 1e-5f);

    float4 g  = *(const float4*)(gamma + tid * 4);
    float4 be = *(const float4*)(beta + tid * 4);
    float4 o4;
    o4.x = d0 * rstd * g.x + be.x;
    o4.y = d1 * rstd * g.y + be.y;
    o4.z = d2 * rstd * g.z + be.z;
    o4.w = d3 * rstd * g.w + be.w;
    if (ROUND) {
        o4.x = to_tf32(o4.x); o4.y = to_tf32(o4.y);
        o4.z = to_tf32(o4.z); o4.w = to_tf32(o4.w);
    }
    *(float4*)(out + base) = o4;
}

// ============================================================================
// Launch sequence (graph-capturable)
// ============================================================================
extern "C" void kernel_launch(void* const* d_in, const int* in_sizes, int n_in,
                              void* d_out, int out_size)
{
    const float* tokens = (const float*)d_in[0];
    const float* Wq = (const float*)d_in[1];
    const float* bq = (const float*)d_in[2];
    const float* Wk = (const float*)d_in[3];
    const float* bk = (const float*)d_in[4];
    const float* Wv = (const float*)d_in[5];
    const float* bv = (const float*)d_in[6];
    const float* ds = (const float*)d_in[7];
    const float* W1 = (const float*)d_in[8];
    const float* b1 = (const float*)d_in[9];
    const float* W2 = (const float*)d_in[10];
    const float* b2 = (const float*)d_in[11];
    const float* g1 = (const float*)d_in[12];
    const float* be1 = (const float*)d_in[13];
    const float* g2 = (const float*)d_in[14];
    const float* be2 = (const float*)d_in[15];
    float* out = (float*)d_out;

    float *q, *k, *v, *attn, *x, *y, *h, *s;
    float *tokr, *wq, *wk, *wv, *w1, *w2;
    cudaGetSymbolAddress((void**)&q, g_q);
    cudaGetSymbolAddress((void**)&k, g_k);
    cudaGetSymbolAddress((void**)&v, g_v);
    cudaGetSymbolAddress((void**)&attn, g_attn);
    cudaGetSymbolAddress((void**)&x, g_x);
    cudaGetSymbolAddress((void**)&y, g_y);
    cudaGetSymbolAddress((void**)&h, g_h);
    cudaGetSymbolAddress((void**)&s, g_s);
    cudaGetSymbolAddress((void**)&tokr, g_tokr);
    cudaGetSymbolAddress((void**)&wq, g_wq);
    cudaGetSymbolAddress((void**)&wk, g_wk);
    cudaGetSymbolAddress((void**)&wv, g_wv);
    cudaGetSymbolAddress((void**)&w1, g_w1);
    cudaGetSymbolAddress((void**)&w2, g_w2);

    // Raise dynamic smem limit for GEMM kernels (idempotent, capture-safe).
    cudaFuncSetAttribute(qkv_kernel, cudaFuncAttributeMaxDynamicSharedMemorySize, SMEM_BYTES);
    cudaFuncSetAttribute(gemm_tc<0, 0, 1, 0>, cudaFuncAttributeMaxDynamicSharedMemorySize, SMEM_BYTES);
    cudaFuncSetAttribute(gemm_tc<0, 1, 0, 0>, cudaFuncAttributeMaxDynamicSharedMemorySize, SMEM_BYTES);
    cudaFuncSetAttribute(gemm_tc<1, 0, 0, 1>, cudaFuncAttributeMaxDynamicSharedMemorySize, SMEM_BYTES);
    cudaFuncSetAttribute(gemm_tc<0, 0, 0, 0>, cudaFuncAttributeMaxDynamicSharedMemorySize, SMEM_BYTES);

    // --- pre-round raw GEMM inputs to tf32 (rna) ---
    round_kernel<<<(NTOK * D_MODEL / 4 + 255) / 256, 256>>>(tokens, tokr, NTOK * D_MODEL / 4);
    round_kernel<<<(D_MODEL * D_MODEL / 4 + 255) / 256, 256>>>(Wq, wq, D_MODEL * D_MODEL / 4);
    round_kernel<<<(D_MODEL * D_MODEL / 4 + 255) / 256, 256>>>(Wk, wk, D_MODEL * D_MODEL / 4);
    round_kernel<<<(D_MODEL * D_MODEL / 4 + 255) / 256, 256>>>(Wv, wv, D_MODEL * D_MODEL / 4);
    round_kernel<<<(D_MODEL * HDIM / 4 + 255) / 256, 256>>>(W1, w1, D_MODEL * HDIM / 4);
    round_kernel<<<(HDIM * D_MODEL / 4 + 255) / 256, 256>>>(W2, w2, HDIM * D_MODEL / 4);

    // --- QKV (fused; outputs tf32-rounded) ---
    qkv_kernel<<<dim3(D_MODEL / 128, NTOK / 128, 3), 256, SMEM_BYTES>>>(
        tokr, wq, wk, wv, bq, bk, bv, q, k, v);

    // --- raw scores S = Q @ K^T (above-diagonal tiles skipped) ---
    gemm_tc<0, 0, 1, 0><<<dim3(TSEQ / 128, TSEQ / 128, NB), 256, SMEM_BYTES>>>(
        q, k, nullptr, s, TSEQ, TSEQ, D_MODEL,
        (long)TSEQ * D_MODEL, (long)TSEQ * D_MODEL, (long)TSEQ * TSEQ);

    // --- masked softmax (distance bias + 1/sqrt(d)); outputs tf32-rounded ---
    softmax_kernel<<<dim3(TSEQ, NB), 256>>>(s, ds);

    // --- attn = P @ V, K clamped to causal extent ---
    gemm_tc<0, 1, 0, 0><<<dim3(D_MODEL / 128, TSEQ / 128, NB), 256, SMEM_BYTES>>>(
        s, v, nullptr, attn, TSEQ, D_MODEL, TSEQ,
        (long)TSEQ * TSEQ, (long)TSEQ * D_MODEL, (long)TSEQ * D_MODEL);

    // --- x = LN(tokens + attn) (tf32-rounded; feeds FFN1 + residual) ---
    ln_kernel<1><<<NTOK, 128>>>(tokens, attn, g1, be1, x);

    // --- h = relu(x @ W1 + b1) (tf32-rounded) ---
    gemm_tc<1, 0, 0, 1><<<dim3(HDIM / 128, NTOK / 128, 1), 256, SMEM_BYTES>>>(
        x, w1, b1, h, NTOK, HDIM, D_MODEL, 0, 0, 0);

    // --- y = h @ W2 + b2 (full precision out) ---
    gemm_tc<0, 0, 0, 0><<<dim3(D_MODEL / 128, NTOK / 128, 1), 256, SMEM_BYTES>>>(
        h, w2, b2, y, NTOK, D_MODEL, HDIM, 0, 0, 0);

    // --- z = LN(y + x) ---
    ln_kernel<0><<<NTOK, 128>>>(y, x, g2, be2, out);
}

// round 6
// speedup vs baseline: 1.0368x; 1.0368x over previous
#include <cuda_runtime.h>
#include <math.h>
#include <stdint.h>

// Problem constants
#define D_MODEL 512
#define HDIM    2048
#define TSEQ    4096
#define NB      2
#define NTOK    (NB * TSEQ)  // 8192

#define STAGE_FLOATS 9216                    // A(128*36=4608) + B(<=4608) per stage
#define NSTAGE 3
#define SMEM_BYTES   (NSTAGE * STAGE_FLOATS * 4)  // 110592

// -------- static scratch (allocation-free per harness rules) --------
__device__ float g_q[(size_t)NTOK * D_MODEL];
__device__ float g_k[(size_t)NTOK * D_MODEL];
__device__ float g_v[(size_t)NTOK * D_MODEL];
__device__ float g_attn[(size_t)NTOK * D_MODEL];
__device__ float g_x[(size_t)NTOK * D_MODEL];
__device__ float g_y[(size_t)NTOK * D_MODEL];
__device__ float g_h[(size_t)NTOK * HDIM];
__device__ float g_s[(size_t)NB * TSEQ * TSEQ];
// tf32-pre-rounded copies of raw inputs
__device__ float g_tokr[(size_t)NTOK * D_MODEL];
__device__ float g_wq[(size_t)D_MODEL * D_MODEL];
__device__ float g_wk[(size_t)D_MODEL * D_MODEL];
__device__ float g_wv[(size_t)D_MODEL * D_MODEL];
__device__ float g_w1[(size_t)D_MODEL * HDIM];
__device__ float g_w2[(size_t)HDIM * D_MODEL];

// ---------------------------------------------------------------------------
// helpers
// ---------------------------------------------------------------------------
__device__ __forceinline__ float to_tf32(float x) {
    uint32_t u;
    asm("cvt.rna.tf32.f32 %0, %1;" : "=r"(u) : "f"(x));
    return __uint_as_float(u);
}

__device__ __forceinline__ void mma_tf32(float c[4], const float a[4], const float b[2]) {
    asm volatile(
        "mma.sync.aligned.m16n8k8.row.col.f32.tf32.tf32.f32 "
        "{%0,%1,%2,%3}, {%4,%5,%6,%7}, {%8,%9}, {%0,%1,%2,%3};"
        : "+f"(c[0]), "+f"(c[1]), "+f"(c[2]), "+f"(c[3])
        : "r"(__float_as_uint(a[0])), "r"(__float_as_uint(a[1])),
          "r"(__float_as_uint(a[2])), "r"(__float_as_uint(a[3])),
          "r"(__float_as_uint(b[0])), "r"(__float_as_uint(b[1])));
}

__device__ __forceinline__ uint32_t smem_u32(const void* p) {
    return (uint32_t)__cvta_generic_to_shared(p);
}
__device__ __forceinline__ void cp16(uint32_t d, const void* s) {
    asm volatile("cp.async.cg.shared.global [%0], [%1], 16;" :: "r"(d), "l"(s));
}
__device__ __forceinline__ void cp_commit() {
    asm volatile("cp.async.commit_group;");
}
template <int N>
__device__ __forceinline__ void cp_wait() {
    asm volatile("cp.async.wait_group %0;" :: "n"(N));
}

// ============================================================================
// tf32 tensor-core GEMM body. 128 threads = 4 warps, each owning a 64x64
// warp tile (halves smem read bytes/FLOP vs 64x32). cp.async 3-stage
// pipeline, prefetch depth 2, one barrier per k-iter.
// All inputs must already be tf32-representable (HMMA truncation lossless).
//   TRANSB=0: B is KxN; smem [k][n] stride 136.  TRANSB=1: B is NxK; [n][k] s36.
//   KLIMIT=1: K clamped to (blockIdx.y+1)*128 (causal P@V).
//   ROUND_OUT=1: epilogue rounds output to tf32 (rna).
// ============================================================================
template <int RELU, int KLIMIT, int TRANSB, int ROUND_OUT>
__device__ __forceinline__ void gemm_body(
    const float* __restrict__ A, const float* __restrict__ B,
    const float* __restrict__ bias, float* __restrict__ C,
    int M, int N, int K)
{
    extern __shared__ float smem[];
    const int tid = threadIdx.x;
    const int m0 = blockIdx.y * 128;
    const int n0 = blockIdx.x * 128;
    const int Keff = KLIMIT ? min(K, ((int)blockIdx.y + 1) * 128) : K;
    const int NUMK = Keff >> 5;  // always >= 4 here

    const int lane = tid & 31;
    const int gid  = lane >> 2;
    const int tg   = lane & 3;
    const int warp = tid >> 5;          // 0..3
    const int mw   = (warp >> 1) * 64;  // warp row offset
    const int nw   = (warp & 1) * 64;   // warp col offset

    auto load_stage = [&](int s) {
        float* As = smem + (s % NSTAGE) * STAGE_FLOATS;
        float* Bs = As + 4608;
        const int kt = s << 5;
#pragma unroll
        for (int i = 0; i < 8; i++) {
            int idx = tid + i * 128;
            int row = idx >> 3;
            int c4  = (idx & 7) << 2;
            cp16(smem_u32(As + row * 36 + c4), A + (size_t)(m0 + row) * K + kt + c4);
            if (TRANSB) {
                cp16(smem_u32(Bs + row * 36 + c4), B + (size_t)(n0 + row) * K + kt + c4);
            } else {
                int kr = idx >> 5;
                int nc = (idx & 31) << 2;
                cp16(smem_u32(Bs + kr * 136 + nc), B + (size_t)(kt + kr) * N + n0 + nc);
            }
        }
    };

    float acc[4][8][4] = {};

    load_stage(0); cp_commit();
    load_stage(1); cp_commit();

    for (int k = 0; k < NUMK; k++) {
        cp_wait<1>();        // stage k resident
        __syncthreads();     // visibility + all warps done with stage k-1's slot
        if (k + 2 < NUMK) load_stage(k + 2);  // into slot (k-1)%3: safe post-barrier
        cp_commit();

        const float* As = smem + (k % NSTAGE) * STAGE_FLOATS;
        const float* Bs = As + 4608;

#pragma unroll
        for (int ks = 0; ks < 4; ks++) {
            const int kk = ks * 8;
            float a[4][4];
#pragma unroll
            for (int i = 0; i < 4; i++) {
                int mb = (mw + i * 16 + gid) * 36;
                a[i][0] = As[mb + kk + tg];
                a[i][1] = As[mb + 8 * 36 + kk + tg];
                a[i][2] = As[mb + kk + tg + 4];
                a[i][3] = As[mb + 8 * 36 + kk + tg + 4];
            }
            float b[8][2];
#pragma unroll
            for (int j = 0; j < 8; j++) {
                if (TRANSB) {
                    int nb = (nw + j * 8 + gid) * 36;
                    b[j][0] = Bs[nb + kk + tg];
                    b[j][1] = Bs[nb + kk + tg + 4];
                } else {
                    b[j][0] = Bs[(kk + tg) * 136 + nw + j * 8 + gid];
                    b[j][1] = Bs[(kk + tg + 4) * 136 + nw + j * 8 + gid];
                }
            }
#pragma unroll
            for (int i = 0; i < 4; i++)
#pragma unroll
                for (int j = 0; j < 8; j++) mma_tf32(acc[i][j], a[i], b[j]);
        }
    }

#pragma unroll
    for (int i = 0; i < 4; i++) {
        int m = m0 + mw + i * 16 + gid;
#pragma unroll
        for (int j = 0; j < 8; j++) {
            int n = n0 + nw + j * 8 + tg * 2;
            float2 lo = make_float2(acc[i][j][0], acc[i][j][1]);
            float2 hi = make_float2(acc[i][j][2], acc[i][j][3]);
            if (bias) {
                float b0 = bias[n], b1 = bias[n + 1];
                lo.x += b0; lo.y += b1; hi.x += b0; hi.y += b1;
            }
            if (RELU) {
                lo.x = fmaxf(lo.x, 0.f); lo.y = fmaxf(lo.y, 0.f);
                hi.x = fmaxf(hi.x, 0.f); hi.y = fmaxf(hi.y, 0.f);
            }
            if (ROUND_OUT) {
                lo.x = to_tf32(lo.x); lo.y = to_tf32(lo.y);
                hi.x = to_tf32(hi.x); hi.y = to_tf32(hi.y);
            }
            *(float2*)(C + (size_t)m * N + n) = lo;
            *(float2*)(C + (size_t)(m + 8) * N + n) = hi;
        }
    }
}

template <int RELU, int KLIMIT, int TRANSB, int ROUND_OUT>
__global__ __launch_bounds__(128, 2) void gemm_tc(
    const float* __restrict__ Aall, const float* __restrict__ Ball,
    const float* __restrict__ bias, float* __restrict__ Call,
    int M, int N, int K, long sA, long sB, long sC)
{
    if (TRANSB && blockIdx.x > blockIdx.y) return;  // fully-masked score tile
    gemm_body<RELU, KLIMIT, TRANSB, ROUND_OUT>(
        Aall + (size_t)blockIdx.z * sA, Ball + (size_t)blockIdx.z * sB,
        bias, Call + (size_t)blockIdx.z * sC, M, N, K);
}

// Fused QKV: one launch, blockIdx.z selects projection.
__global__ __launch_bounds__(128, 2) void qkv_kernel(
    const float* __restrict__ tok,
    const float* __restrict__ Wq, const float* __restrict__ Wk, const float* __restrict__ Wv,
    const float* __restrict__ bq, const float* __restrict__ bk, const float* __restrict__ bv,
    float* __restrict__ q, float* __restrict__ k, float* __restrict__ v)
{
    const float* W = blockIdx.z == 0 ? Wq : (blockIdx.z == 1 ? Wk : Wv);
    const float* b = blockIdx.z == 0 ? bq : (blockIdx.z == 1 ? bk : bv);
    float*       C = blockIdx.z == 0 ? q  : (blockIdx.z == 1 ? k  : v);
    gemm_body<0, 0, 0, 1>(tok, W, b, C, NTOK, D_MODEL, D_MODEL);
}

// Pre-round raw inputs to tf32 (rna), vectorized.
__global__ __launch_bounds__(256) void round_kernel(
    const float* __restrict__ in, float* __restrict__ out, int n4)
{
    int i = blockIdx.x * 256 + threadIdx.x;
    if (i < n4) {
        float4 v = ((const float4*)in)[i];
        v.x = to_tf32(v.x); v.y = to_tf32(v.y);
        v.z = to_tf32(v.z); v.w = to_tf32(v.w);
        ((float4*)out)[i] = v;
    }
}

// ---------------------------------------------------------------------------
// FMA-only exp (input <= 0 after max-subtract; clamped).
// ---------------------------------------------------------------------------
__device__ __forceinline__ float fast_exp(float x) {
    x = fmaxf(x, -87.0f);
    float z = x * 1.4426950408889634f;
    float n = rintf(z);
    float t = z - n;
    float p = 1.5403530e-4f;
    p = fmaf(p, t, 1.3333558e-3f);
    p = fmaf(p, t, 9.6181291e-3f);
    p = fmaf(p, t, 5.5504109e-2f);
    p = fmaf(p, t, 2.4022651e-1f);
    p = fmaf(p, t, 6.9314718e-1f);
    p = fmaf(p, t, 1.0f);
    int e = (int)n;
    return p * __int_as_float((e + 127) << 23);
}

// ============================================================================
// Row softmax (in-place, register-resident). Output rounded to tf32 so the
// PV GEMM's cp.async truncation is lossless. Zeros written up to next 128.
// ============================================================================
__global__ __launch_bounds__(256) void softmax_kernel(
    float* __restrict__ S, const float* __restrict__ ds_ptr)
{
    __shared__ float red[8];

    const int t = blockIdx.x;
    const int b = blockIdx.y;
    const int tid = threadIdx.x;
    const int lane = tid & 31;
    const int wid  = tid >> 5;
    float* row = S + ((size_t)b * TSEQ + t) * TSEQ;

    const float ds = *ds_ptr;
    const float scale = rsqrtf((float)D_MODEL);
    const int len = t + 1;
    const int limit = ((t >> 7) + 1) << 7;

    float v[16];
    float mx = -1e30f;
#pragma unroll
    for (int it = 0; it < 16; it++) {
        int s = tid + it * 256;
        float val = -1e30f;
        if (s < len) val = (row[s] - ds * (float)(t - s)) * scale;
        v[it] = val;
        mx = fmaxf(mx, val);
    }
#pragma unroll
    for (int o = 16; o; o >>= 1) mx = fmaxf(mx, __shfl_xor_sync(0xffffffffu, mx, o));
    if (lane == 0) red[wid] = mx;
    __syncthreads();
    float mall = -1e30f;
#pragma unroll
    for (int w = 0; w < 8; w++) mall = fmaxf(mall, red[w]);
    __syncthreads();

    float sum = 0.f;
#pragma unroll
    for (int it = 0; it < 16; it++) {
        int s = tid + it * 256;
        float e = (s < len) ? fast_exp(v[it] - mall) : 0.f;
        v[it] = e;
        sum += e;
    }
#pragma unroll
    for (int o = 16; o; o >>= 1) sum += __shfl_xor_sync(0xffffffffu, sum, o);
    if (lane == 0) red[wid] = sum;
    __syncthreads();
    float sall = 0.f;
#pragma unroll
    for (int w = 0; w < 8; w++) sall += red[w];
    const float inv = 1.0f / sall;

#pragma unroll
    for (int it = 0; it < 16; it++) {
        int s = tid + it * 256;
        if (s < len)        row[s] = to_tf32(v[it] * inv);
        else if (s < limit) row[s] = 0.f;
    }
}

// ============================================================================
// LayerNorm over last dim (512): out = LN(A + R) * gamma + beta.
// ROUND=1 rounds the output to tf32 (feeds a GEMM).
// ============================================================================
template <int ROUND>
__global__ __launch_bounds__(128) void ln_kernel(
    const float* __restrict__ A, const float* __restrict__ R,
    const float* __restrict__ gamma, const float* __restrict__ beta,
    float* __restrict__ out)
{
    __shared__ float sh[4];
    const int row = blockIdx.x;
    const int tid = threadIdx.x;
    const size_t base = (size_t)row * D_MODEL + tid * 4;

    float4 a = *(const float4*)(A + base);
    float4 r = *(const float4*)(R + base);
    float x0 = a.x + r.x, x1 = a.y + r.y, x2 = a.z + r.z, x3 = a.w + r.w;

    float s = x0 + x1 + x2 + x3;
    for (int o = 16; o; o >>= 1) s += __shfl_xor_sync(0xffffffffu, s, o);
    if ((tid & 31) == 0) sh[tid >> 5] = s;
    __syncthreads();
    const float mean = (sh[0] + sh[1] + sh[2] + sh[3]) * (1.0f / D_MODEL);
    __syncthreads();

    float d0 = x0 - mean, d1 = x1 - mean, d2 = x2 - mean, d3 = x3 - mean;
    float sq = d0 * d0 + d1 * d1 + d2 * d2 + d3 * d3;
    for (int o = 16; o; o >>= 1) sq += __shfl_xor_sync(0xffffffffu, sq, o);
    if ((tid & 31) == 0) sh[tid >> 5] = sq;
    __syncthreads();
    const float var = (sh[0] + sh[1] + sh[2] + sh[3]) * (1.0f / D_MODEL);
    const float rstd = rsqrtf(var + 1e-5f);

    float4 g  = *(const float4*)(gamma + tid * 4);
    float4 be = *(const float4*)(beta + tid * 4);
    float4 o4;
    o4.x = d0 * rstd * g.x + be.x;
    o4.y = d1 * rstd * g.y + be.y;
    o4.z = d2 * rstd * g.z + be.z;
    o4.w = d3 * rstd * g.w + be.w;
    if (ROUND) {
        o4.x = to_tf32(o4.x); o4.y = to_tf32(o4.y);
        o4.z = to_tf32(o4.z); o4.w = to_tf32(o4.w);
    }
    *(float4*)(out + base) = o4;
}

// ============================================================================
// Launch sequence (graph-capturable)
// ============================================================================
extern "C" void kernel_launch(void* const* d_in, const int* in_sizes, int n_in,
                              void* d_out, int out_size)
{
    const float* tokens = (const float*)d_in[0];
    const float* Wq = (const float*)d_in[1];
    const float* bq = (const float*)d_in[2];
    const float* Wk = (const float*)d_in[3];
    const float* bk = (const float*)d_in[4];
    const float* Wv = (const float*)d_in[5];
    const float* bv = (const float*)d_in[6];
    const float* ds = (const float*)d_in[7];
    const float* W1 = (const float*)d_in[8];
    const float* b1 = (const float*)d_in[9];
    const float* W2 = (const float*)d_in[10];
    const float* b2 = (const float*)d_in[11];
    const float* g1 = (const float*)d_in[12];
    const float* be1 = (const float*)d_in[13];
    const float* g2 = (const float*)d_in[14];
    const float* be2 = (const float*)d_in[15];
    float* out = (float*)d_out;

    float *q, *k, *v, *attn, *x, *y, *h, *s;
    float *tokr, *wq, *wk, *wv, *w1, *w2;
    cudaGetSymbolAddress((void**)&q, g_q);
    cudaGetSymbolAddress((void**)&k, g_k);
    cudaGetSymbolAddress((void**)&v, g_v);
    cudaGetSymbolAddress((void**)&attn, g_attn);
    cudaGetSymbolAddress((void**)&x, g_x);
    cudaGetSymbolAddress((void**)&y, g_y);
    cudaGetSymbolAddress((void**)&h, g_h);
    cudaGetSymbolAddress((void**)&s, g_s);
    cudaGetSymbolAddress((void**)&tokr, g_tokr);
    cudaGetSymbolAddress((void**)&wq, g_wq);
    cudaGetSymbolAddress((void**)&wk, g_wk);
    cudaGetSymbolAddress((void**)&wv, g_wv);
    cudaGetSymbolAddress((void**)&w1, g_w1);
    cudaGetSymbolAddress((void**)&w2, g_w2);

    // Raise dynamic smem limit for GEMM kernels (idempotent, capture-safe).
    cudaFuncSetAttribute(qkv_kernel, cudaFuncAttributeMaxDynamicSharedMemorySize, SMEM_BYTES);
    cudaFuncSetAttribute(gemm_tc<0, 0, 1, 0>, cudaFuncAttributeMaxDynamicSharedMemorySize, SMEM_BYTES);
    cudaFuncSetAttribute(gemm_tc<0, 1, 0, 0>, cudaFuncAttributeMaxDynamicSharedMemorySize, SMEM_BYTES);
    cudaFuncSetAttribute(gemm_tc<1, 0, 0, 1>, cudaFuncAttributeMaxDynamicSharedMemorySize, SMEM_BYTES);
    cudaFuncSetAttribute(gemm_tc<0, 0, 0, 0>, cudaFuncAttributeMaxDynamicSharedMemorySize, SMEM_BYTES);

    // --- pre-round raw GEMM inputs to tf32 (rna) ---
    round_kernel<<<(NTOK * D_MODEL / 4 + 255) / 256, 256>>>(tokens, tokr, NTOK * D_MODEL / 4);
    round_kernel<<<(D_MODEL * D_MODEL / 4 + 255) / 256, 256>>>(Wq, wq, D_MODEL * D_MODEL / 4);
    round_kernel<<<(D_MODEL * D_MODEL / 4 + 255) / 256, 256>>>(Wk, wk, D_MODEL * D_MODEL / 4);
    round_kernel<<<(D_MODEL * D_MODEL / 4 + 255) / 256, 256>>>(Wv, wv, D_MODEL * D_MODEL / 4);
    round_kernel<<<(D_MODEL * HDIM / 4 + 255) / 256, 256>>>(W1, w1, D_MODEL * HDIM / 4);
    round_kernel<<<(HDIM * D_MODEL / 4 + 255) / 256, 256>>>(W2, w2, HDIM * D_MODEL / 4);

    // --- QKV (fused; outputs tf32-rounded) ---
    qkv_kernel<<<dim3(D_MODEL / 128, NTOK / 128, 3), 128, SMEM_BYTES>>>(
        tokr, wq, wk, wv, bq, bk, bv, q, k, v);

    // --- raw scores S = Q @ K^T (above-diagonal tiles skipped) ---
    gemm_tc<0, 0, 1, 0><<<dim3(TSEQ / 128, TSEQ / 128, NB), 128, SMEM_BYTES>>>(
        q, k, nullptr, s, TSEQ, TSEQ, D_MODEL,
        (long)TSEQ * D_MODEL, (long)TSEQ * D_MODEL, (long)TSEQ * TSEQ);

    // --- masked softmax (distance bias + 1/sqrt(d)); outputs tf32-rounded ---
    softmax_kernel<<<dim3(TSEQ, NB), 256>>>(s, ds);

    // --- attn = P @ V, K clamped to causal extent ---
    gemm_tc<0, 1, 0, 0><<<dim3(D_MODEL / 128, TSEQ / 128, NB), 128, SMEM_BYTES>>>(
        s, v, nullptr, attn, TSEQ, D_MODEL, TSEQ,
        (long)TSEQ * TSEQ, (long)TSEQ * D_MODEL, (long)TSEQ * D_MODEL);

    // --- x = LN(tokens + attn) (tf32-rounded; feeds FFN1 + residual) ---
    ln_kernel<1><<<NTOK, 128>>>(tokens, attn, g1, be1, x);

    // --- h = relu(x @ W1 + b1) (tf32-rounded) ---
    gemm_tc<1, 0, 0, 1><<<dim3(HDIM / 128, NTOK / 128, 1), 128, SMEM_BYTES>>>(
        x, w1, b1, h, NTOK, HDIM, D_MODEL, 0, 0, 0);

    // --- y = h @ W2 + b2 (full precision out) ---
    gemm_tc<0, 0, 0, 0><<<dim3(D_MODEL / 128, NTOK / 128, 1), 128, SMEM_BYTES>>>(
        h, w2, b2, y, NTOK, D_MODEL, HDIM, 0, 0, 0);

    // --- z = LN(y + x) ---
    ln_kernel<0><<<NTOK, 128>>>(y, x, g2, be2, out);
}

// round 10
// speedup vs baseline: 1.0674x; 1.0295x over previous
#include <cuda_runtime.h>
#include <cuda.h>
#include <math.h>
#include <stdint.h>

// Problem constants
#define D_MODEL 512
#define HDIM    2048
#define TSEQ    4096
#define NB      2
#define NTOK    (NB * TSEQ)  // 8192

// ---- old (PV) kernel smem config ----
#define STAGE_FLOATS 9216
#define NSTAGE 3
#define PV_SMEM_BYTES (NSTAGE * STAGE_FLOATS * 4)

// ---- new TMA kernel config ----
#define TBM 256
#define TBN 128
#define TBK 32
#define A_STAGE_B 32768            // 256 rows * 128 B
#define B_STAGE_B 16384            // 128 rows * 128 B
#define STAGE_B   (A_STAGE_B + B_STAGE_B)   // 49152
#define TSMEM_BYTES (2 * STAGE_B + 128)     // + mbarriers

// -------- static scratch (allocation-free per harness rules) --------
__device__ float g_q[(size_t)NTOK * D_MODEL];
__device__ float g_k[(size_t)NTOK * D_MODEL];
__device__ float g_v[(size_t)NTOK * D_MODEL];
__device__ float g_attn[(size_t)NTOK * D_MODEL];
__device__ float g_x[(size_t)NTOK * D_MODEL];
__device__ float g_y[(size_t)NTOK * D_MODEL];
__device__ float g_h[(size_t)NTOK * HDIM];
__device__ float g_s[(size_t)NB * TSEQ * TSEQ];
__device__ float g_tokr[(size_t)NTOK * D_MODEL];
// transposed tf32-rounded weights ([N,K] layouts)
__device__ float g_wqkvT[(size_t)3 * D_MODEL * D_MODEL];  // rows: 1536, cols: 512
__device__ float g_w1T[(size_t)HDIM * D_MODEL];           // [2048, 512]
__device__ float g_w2T[(size_t)D_MODEL * HDIM];           // [512, 2048]

// ---------------------------------------------------------------------------
// helpers
// ---------------------------------------------------------------------------
__device__ __forceinline__ float to_tf32(float x) {
    uint32_t u;
    asm("cvt.rna.tf32.f32 %0, %1;" : "=r"(u) : "f"(x));
    return __uint_as_float(u);
}

__device__ __forceinline__ void mma_tf32(float c[4], const float a[4], const float b[2]) {
    asm volatile(
        "mma.sync.aligned.m16n8k8.row.col.f32.tf32.tf32.f32 "
        "{%0,%1,%2,%3}, {%4,%5,%6,%7}, {%8,%9}, {%0,%1,%2,%3};"
        : "+f"(c[0]), "+f"(c[1]), "+f"(c[2]), "+f"(c[3])
        : "r"(__float_as_uint(a[0])), "r"(__float_as_uint(a[1])),
          "r"(__float_as_uint(a[2])), "r"(__float_as_uint(a[3])),
          "r"(__float_as_uint(b[0])), "r"(__float_as_uint(b[1])));
}

__device__ __forceinline__ uint32_t smem_u32(const void* p) {
    return (uint32_t)__cvta_generic_to_shared(p);
}
__device__ __forceinline__ void cp16(uint32_t d, const void* s) {
    asm volatile("cp.async.cg.shared.global [%0], [%1], 16;" :: "r"(d), "l"(s));
}
__device__ __forceinline__ void cp_commit() {
    asm volatile("cp.async.commit_group;");
}
template <int N>
__device__ __forceinline__ void cp_wait() {
    asm volatile("cp.async.wait_group %0;" :: "n"(N));
}

// ---- mbarrier / TMA primitives ----
__device__ __forceinline__ void mbar_init(uint32_t a, uint32_t cnt) {
    asm volatile("mbarrier.init.shared.b64 [%0], %1;" :: "r"(a), "r"(cnt) : "memory");
}
__device__ __forceinline__ void mbar_expect(uint32_t a, uint32_t tx) {
    asm volatile("mbarrier.arrive.expect_tx.shared.b64 _, [%0], %1;" :: "r"(a), "r"(tx) : "memory");
}
__device__ __forceinline__ void mbar_wait(uint32_t a, int parity) {
    asm volatile(
        "{\n\t"
        ".reg .pred P1;\n\t"
        "WAIT_LOOP_%=:\n\t"
        "mbarrier.try_wait.parity.acquire.cta.shared::cta.b64 P1, [%0], %1, 0x989680;\n\t"
        "@P1 bra.uni WAIT_DONE_%=;\n\t"
        "bra.uni WAIT_LOOP_%=;\n\t"
        "WAIT_DONE_%=:\n\t"
        "}"
        :: "r"(a), "r"(parity) : "memory");
}
__device__ __forceinline__ void tma2d(uint32_t dst, const void* map, int cx, int cy, uint32_t bar) {
    asm volatile(
        "cp.async.bulk.tensor.2d.shared::cta.global.tile.mbarrier::complete_tx::bytes "
        "[%0], [%1, {%2, %3}], [%4];"
        :: "r"(dst), "l"(map), "r"(cx), "r"(cy), "r"(bar) : "memory");
}

// SW128-swizzled fp32 element in a [rows][32] tile with 128B rows
__device__ __forceinline__ float SWF(const char* base, int row, int col) {
    int off = row * 128 + col * 4;
    off ^= (off >> 3) & 0x70;
    return *(const float*)(base + off);
}

// ============================================================================
// TMA-fed tf32 GEMM: C[TBM x TBN] per CTA, 256 threads, 8 warps of 64x64.
// A map: row-major [Mtot, K] fp32, box (32, 256).  B map: [Ntot, K], box (32,128)
// (B pre-transposed; computes C = A @ B^T).  Double-buffered TMA + mbarrier.
//   CAUSAL=1: skip tiles with n0 > m0+TBM-1 (scores);
//   MULTI=1: blockIdx.z selects out/bias from {o0,o1,o2}/{b0,b1,b2} (QKV),
//   else out = o0 + z*ozs, bias = b0.
// ============================================================================
template <int RELU, int ROUND, int CAUSAL, int MULTI>
__global__ __launch_bounds__(256, 1) void gemm_tma(
    const __grid_constant__ CUtensorMap tmA,
    const __grid_constant__ CUtensorMap tmB,
    const float* __restrict__ b0, const float* __restrict__ b1, const float* __restrict__ b2,
    float* __restrict__ o0, float* __restrict__ o1, float* __restrict__ o2,
    int Cstride, int K, int za, int zb, long ozs)
{
    if (CAUSAL && (int)blockIdx.x > 2 * (int)blockIdx.y + 1) return;

    extern __shared__ __align__(1024) char smem[];
    const int tid = threadIdx.x;
    const int z   = blockIdx.z;
    const int m0  = blockIdx.y * TBM;
    const int n0  = blockIdx.x * TBN;
    const int ya  = m0 + z * za;  // A row coord
    const int yb  = n0 + z * zb;  // B row coord
    const uint32_t sbase = smem_u32(smem);
    const uint32_t bar0 = sbase + 2 * STAGE_B;
    const uint32_t bar1 = bar0 + 8;
    const int NS = K / TBK;

    if (tid == 0) { mbar_init(bar0, 1); mbar_init(bar1, 1); }
    __syncthreads();
    if (tid == 0) {
        mbar_expect(bar0, STAGE_B);
        tma2d(sbase, &tmA, 0, ya, bar0);
        tma2d(sbase + A_STAGE_B, &tmB, 0, yb, bar0);
        mbar_expect(bar1, STAGE_B);
        tma2d(sbase + STAGE_B, &tmA, TBK, ya, bar1);
        tma2d(sbase + STAGE_B + A_STAGE_B, &tmB, TBK, yb, bar1);
    }

    const int lane = tid & 31;
    const int gid  = lane >> 2;
    const int tg   = lane & 3;
    const int warp = tid >> 5;           // 0..7
    const int mw   = (warp >> 1) * 64;   // 0,64,128,192
    const int nw   = (warp & 1) * 64;    // 0,64

    float acc[4][8][4] = {};
    int ph0 = 0, ph1 = 0;

    for (int s = 0; s < NS; s++) {
        const int b = s & 1;
        if (b == 0) { mbar_wait(bar0, ph0 & 1); ph0++; }
        else        { mbar_wait(bar1, ph1 & 1); ph1++; }

        const char* As = smem + b * STAGE_B;
        const char* Bs = As + A_STAGE_B;

#pragma unroll
        for (int ks = 0; ks < 4; ks++) {
            const int kk = ks * 8;
            float a[4][4];
#pragma unroll
            for (int i = 0; i < 4; i++) {
                int r = mw + i * 16 + gid;
                a[i][0] = SWF(As, r,     kk + tg);
                a[i][1] = SWF(As, r + 8, kk + tg);
                a[i][2] = SWF(As, r,     kk + tg + 4);
                a[i][3] = SWF(As, r + 8, kk + tg + 4);
            }
            float bb[8][2];
#pragma unroll
            for (int j = 0; j < 8; j++) {
                int r = nw + j * 8 + gid;
                bb[j][0] = SWF(Bs, r, kk + tg);
                bb[j][1] = SWF(Bs, r, kk + tg + 4);
            }
#pragma unroll
            for (int i = 0; i < 4; i++)
#pragma unroll
                for (int j = 0; j < 8; j++) mma_tf32(acc[i][j], a[i], bb[j]);
        }
        __syncthreads();  // all warps done with buffer b
        if (tid == 0 && s + 2 < NS) {
            const uint32_t bar = b ? bar1 : bar0;
            mbar_expect(bar, STAGE_B);
            tma2d(sbase + b * STAGE_B, &tmA, (s + 2) * TBK, ya, bar);
            tma2d(sbase + b * STAGE_B + A_STAGE_B, &tmB, (s + 2) * TBK, yb, bar);
        }
    }

    // ---- epilogue ----
    float* C;
    const float* bias;
    if (MULTI) {
        C    = (z == 0) ? o0 : (z == 1) ? o1 : o2;
        bias = (z == 0) ? b0 : (z == 1) ? b1 : b2;
    } else {
        C    = o0 + (size_t)z * ozs;
        bias = b0;
    }
#pragma unroll
    for (int i = 0; i < 4; i++) {
        int m = m0 + mw + i * 16 + gid;
#pragma unroll
        for (int j = 0; j < 8; j++) {
            int n = n0 + nw + j * 8 + tg * 2;
            float2 lo = make_float2(acc[i][j][0], acc[i][j][1]);
            float2 hi = make_float2(acc[i][j][2], acc[i][j][3]);
            if (bias) {
                float u0 = bias[n], u1 = bias[n + 1];
                lo.x += u0; lo.y += u1; hi.x += u0; hi.y += u1;
            }
            if (RELU) {
                lo.x = fmaxf(lo.x, 0.f); lo.y = fmaxf(lo.y, 0.f);
                hi.x = fmaxf(hi.x, 0.f); hi.y = fmaxf(hi.y, 0.f);
            }
            if (ROUND) {
                lo.x = to_tf32(lo.x); lo.y = to_tf32(lo.y);
                hi.x = to_tf32(hi.x); hi.y = to_tf32(hi.y);
            }
            *(float2*)(C + (size_t)m * Cstride + n) = lo;
            *(float2*)(C + (size_t)(m + 8) * Cstride + n) = hi;
        }
    }
}

// ============================================================================
// Old cp.async tf32 GEMM body (kept for PV: TRANSB=0, KLIMIT=1, NN layout)
// 128 threads, 4 warps of 64x64.
// ============================================================================
template <int RELU, int KLIMIT, int TRANSB, int ROUND_OUT>
__device__ __forceinline__ void gemm_body(
    const float* __restrict__ A, const float* __restrict__ B,
    const float* __restrict__ bias, float* __restrict__ C,
    int M, int N, int K)
{
    extern __shared__ float smemf[];
    const int tid = threadIdx.x;
    const int m0 = blockIdx.y * 128;
    const int n0 = blockIdx.x * 128;
    const int Keff = KLIMIT ? min(K, ((int)blockIdx.y + 1) * 128) : K;
    const int NUMK = Keff >> 5;

    const int lane = tid & 31;
    const int gid  = lane >> 2;
    const int tg   = lane & 3;
    const int warp = tid >> 5;
    const int mw   = (warp >> 1) * 64;
    const int nw   = (warp & 1) * 64;

    auto load_stage = [&](int s) {
        float* As = smemf + (s % NSTAGE) * STAGE_FLOATS;
        float* Bs = As + 4608;
        const int kt = s << 5;
#pragma unroll
        for (int i = 0; i < 8; i++) {
            int idx = tid + i * 128;
            int row = idx >> 3;
            int c4  = (idx & 7) << 2;
            cp16(smem_u32(As + row * 36 + c4), A + (size_t)(m0 + row) * K + kt + c4);
            if (TRANSB) {
                cp16(smem_u32(Bs + row * 36 + c4), B + (size_t)(n0 + row) * K + kt + c4);
            } else {
                int kr = idx >> 5;
                int nc = (idx & 31) << 2;
                cp16(smem_u32(Bs + kr * 136 + nc), B + (size_t)(kt + kr) * N + n0 + nc);
            }
        }
    };

    float acc[4][8][4] = {};

    load_stage(0); cp_commit();
    load_stage(1); cp_commit();

    for (int k = 0; k < NUMK; k++) {
        cp_wait<1>();
        __syncthreads();
        if (k + 2 < NUMK) load_stage(k + 2);
        cp_commit();

        const float* As = smemf + (k % NSTAGE) * STAGE_FLOATS;
        const float* Bs = As + 4608;

#pragma unroll
        for (int ks = 0; ks < 4; ks++) {
            const int kk = ks * 8;
            float a[4][4];
#pragma unroll
            for (int i = 0; i < 4; i++) {
                int mb = (mw + i * 16 + gid) * 36;
                a[i][0] = As[mb + kk + tg];
                a[i][1] = As[mb + 8 * 36 + kk + tg];
                a[i][2] = As[mb + kk + tg + 4];
                a[i][3] = As[mb + 8 * 36 + kk + tg + 4];
            }
            float b[8][2];
#pragma unroll
            for (int j = 0; j < 8; j++) {
                if (TRANSB) {
                    int nb = (nw + j * 8 + gid) * 36;
                    b[j][0] = Bs[nb + kk + tg];
                    b[j][1] = Bs[nb + kk + tg + 4];
                } else {
                    b[j][0] = Bs[(kk + tg) * 136 + nw + j * 8 + gid];
                    b[j][1] = Bs[(kk + tg + 4) * 136 + nw + j * 8 + gid];
                }
            }
#pragma unroll
            for (int i = 0; i < 4; i++)
#pragma unroll
                for (int j = 0; j < 8; j++) mma_tf32(acc[i][j], a[i], b[j]);
        }
    }

#pragma unroll
    for (int i = 0; i < 4; i++) {
        int m = m0 + mw + i * 16 + gid;
#pragma unroll
        for (int j = 0; j < 8; j++) {
            int n = n0 + nw + j * 8 + tg * 2;
            float2 lo = make_float2(acc[i][j][0], acc[i][j][1]);
            float2 hi = make_float2(acc[i][j][2], acc[i][j][3]);
            if (bias) {
                float u0 = bias[n], u1 = bias[n + 1];
                lo.x += u0; lo.y += u1; hi.x += u0; hi.y += u1;
            }
            if (RELU) {
                lo.x = fmaxf(lo.x, 0.f); lo.y = fmaxf(lo.y, 0.f);
                hi.x = fmaxf(hi.x, 0.f); hi.y = fmaxf(hi.y, 0.f);
            }
            if (ROUND_OUT) {
                lo.x = to_tf32(lo.x); lo.y = to_tf32(lo.y);
                hi.x = to_tf32(hi.x); hi.y = to_tf32(hi.y);
            }
            *(float2*)(C + (size_t)m * N + n) = lo;
            *(float2*)(C + (size_t)(m + 8) * N + n) = hi;
        }
    }
}

template <int RELU, int KLIMIT, int TRANSB, int ROUND_OUT>
__global__ __launch_bounds__(128, 2) void gemm_tc(
    const float* __restrict__ Aall, const float* __restrict__ Ball,
    const float* __restrict__ bias, float* __restrict__ Call,
    int M, int N, int K, long sA, long sB, long sC)
{
    gemm_body<RELU, KLIMIT, TRANSB, ROUND_OUT>(
        Aall + (size_t)blockIdx.z * sA, Ball + (size_t)blockIdx.z * sB,
        bias, Call + (size_t)blockIdx.z * sC, M, N, K);
}

// ============================================================================
// Pre-pass kernels
// ============================================================================
__global__ __launch_bounds__(256) void round_kernel(
    const float* __restrict__ in, float* __restrict__ out, int n4)
{
    int i = blockIdx.x * 256 + threadIdx.x;
    if (i < n4) {
        float4 v = ((const float4*)in)[i];
        v.x = to_tf32(v.x); v.y = to_tf32(v.y);
        v.z = to_tf32(v.z); v.w = to_tf32(v.w);
        ((float4*)out)[i] = v;
    }
}

// Transpose + tf32-round all weights in one launch. z: 0..2=Wq/Wk/Wv,
// 3=W1, 4=W2. in [R,C] -> out [C,R].
__global__ __launch_bounds__(256) void transpose_all(
    const float* __restrict__ Wq, const float* __restrict__ Wk, const float* __restrict__ Wv,
    const float* __restrict__ W1, const float* __restrict__ W2,
    float* __restrict__ wqkvT, float* __restrict__ w1T, float* __restrict__ w2T)
{
    __shared__ float t[32][33];
    const int z = blockIdx.z;
    const float* in;
    float* out;
    int R, C;
    if (z < 3)      { in = z == 0 ? Wq : z == 1 ? Wk : Wv; out = wqkvT + (size_t)z * D_MODEL * D_MODEL; R = 512; C = 512; }
    else if (z == 3){ in = W1; out = w1T; R = 512; C = 2048; }
    else            { in = W2; out = w2T; R = 2048; C = 512; }
    const int cb = blockIdx.x * 32, rb = blockIdx.y * 32;
    if (cb >= C || rb >= R) return;
    const int tx = threadIdx.x & 31, ty = threadIdx.x >> 5;  // 32x8
    for (int i = ty; i < 32; i += 8) t[i][tx] = in[(size_t)(rb + i) * C + cb + tx];
    __syncthreads();
    for (int i = ty; i < 32; i += 8) out[(size_t)(cb + i) * R + rb + tx] = to_tf32(t[tx][i]);
}

// ---------------------------------------------------------------------------
// FMA-only exp (input <= 0 after max-subtract; clamped).
// ---------------------------------------------------------------------------
__device__ __forceinline__ float fast_exp(float x) {
    x = fmaxf(x, -87.0f);
    float z = x * 1.4426950408889634f;
    float n = rintf(z);
    float t = z - n;
    float p = 1.5403530e-4f;
    p = fmaf(p, t, 1.3333558e-3f);
    p = fmaf(p, t, 9.6181291e-3f);
    p = fmaf(p, t, 5.5504109e-2f);
    p = fmaf(p, t, 2.4022651e-1f);
    p = fmaf(p, t, 6.9314718e-1f);
    p = fmaf(p, t, 1.0f);
    int e = (int)n;
    return p * __int_as_float((e + 127) << 23);
}

// ============================================================================
// Row softmax (in-place, register-resident). tf32-rounded output.
// ============================================================================
__global__ __launch_bounds__(256) void softmax_kernel(
    float* __restrict__ S, const float* __restrict__ ds_ptr)
{
    __shared__ float red[8];

    const int t = blockIdx.x;
    const int b = blockIdx.y;
    const int tid = threadIdx.x;
    const int lane = tid & 31;
    const int wid  = tid >> 5;
    float* row = S + ((size_t)b * TSEQ + t) * TSEQ;

    const float ds = *ds_ptr;
    const float scale = rsqrtf((float)D_MODEL);
    const int len = t + 1;
    const int limit = ((t >> 7) + 1) << 7;

    float v[16];
    float mx = -1e30f;
#pragma unroll
    for (int it = 0; it < 16; it++) {
        int s = tid + it * 256;
        float val = -1e30f;
        if (s < len) val = (row[s] - ds * (float)(t - s)) * scale;
        v[it] = val;
        mx = fmaxf(mx, val);
    }
#pragma unroll
    for (int o = 16; o; o >>= 1) mx = fmaxf(mx, __shfl_xor_sync(0xffffffffu, mx, o));
    if (lane == 0) red[wid] = mx;
    __syncthreads();
    float mall = -1e30f;
#pragma unroll
    for (int w = 0; w < 8; w++) mall = fmaxf(mall, red[w]);
    __syncthreads();

    float sum = 0.f;
#pragma unroll
    for (int it = 0; it < 16; it++) {
        int s = tid + it * 256;
        float e = (s < len) ? fast_exp(v[it] - mall) : 0.f;
        v[it] = e;
        sum += e;
    }
#pragma unroll
    for (int o = 16; o; o >>= 1) sum += __shfl_xor_sync(0xffffffffu, sum, o);
    if (lane == 0) red[wid] = sum;
    __syncthreads();
    float sall = 0.f;
#pragma unroll
    for (int w = 0; w < 8; w++) sall += red[w];
    const float inv = 1.0f / sall;

#pragma unroll
    for (int it = 0; it < 16; it++) {
        int s = tid + it * 256;
        if (s < len)        row[s] = to_tf32(v[it] * inv);
        else if (s < limit) row[s] = 0.f;
    }
}

// ============================================================================
// LayerNorm: out = LN(A + R) * gamma + beta.  ROUND rounds to tf32.
// ============================================================================
template <int ROUND>
__global__ __launch_bounds__(128) void ln_kernel(
    const float* __restrict__ A, const float* __restrict__ R,
    const float* __restrict__ gamma, const float* __restrict__ beta,
    float* __restrict__ out)
{
    __shared__ float sh[4];
    const int row = blockIdx.x;
    const int tid = threadIdx.x;
    const size_t base = (size_t)row * D_MODEL + tid * 4;

    float4 a = *(const float4*)(A + base);
    float4 r = *(const float4*)(R + base);
    float x0 = a.x + r.x, x1 = a.y + r.y, x2 = a.z + r.z, x3 = a.w + r.w;

    float s = x0 + x1 + x2 + x3;
    for (int o = 16; o; o >>= 1) s += __shfl_xor_sync(0xffffffffu, s, o);
    if ((tid & 31) == 0) sh[tid >> 5] = s;
    __syncthreads();
    const float mean = (sh[0] + sh[1] + sh[2] + sh[3]) * (1.0f / D_MODEL);
    __syncthreads();

    float d0 = x0 - mean, d1 = x1 - mean, d2 = x2 - mean, d3 = x3 - mean;
    float sq = d0 * d0 + d1 * d1 + d2 * d2 + d3 * d3;
    for (int o = 16; o; o >>= 1) sq += __shfl_xor_sync(0xffffffffu, sq, o);
    if ((tid & 31) == 0) sh[tid >> 5] = sq;
    __syncthreads();
    const float var = (sh[0] + sh[1] + sh[2] + sh[3]) * (1.0f / D_MODEL);
    const float rstd = rsqrtf(var + 1e-5f);

    float4 g  = *(const float4*)(gamma + tid * 4);
    float4 be = *(const float4*)(beta + tid * 4);
    float4 o4;
    o4.x = d0 * rstd * g.x + be.x;
    o4.y = d1 * rstd * g.y + be.y;
    o4.z = d2 * rstd * g.z + be.z;
    o4.w = d3 * rstd * g.w + be.w;
    if (ROUND) {
        o4.x = to_tf32(o4.x); o4.y = to_tf32(o4.y);
        o4.z = to_tf32(o4.z); o4.w = to_tf32(o4.w);
    }
    *(float4*)(out + base) = o4;
}

// ============================================================================
// Host: tensormap construction via driver entry point (no -lcuda needed)
// ============================================================================
typedef CUresult (*PFN_tmapEncode)(
    CUtensorMap*, CUtensorMapDataType, cuuint32_t, void*,
    const cuuint64_t*, const cuuint64_t*, const cuuint32_t*, const cuuint32_t*,
    CUtensorMapInterleave, CUtensorMapSwizzle, CUtensorMapL2promotion,
    CUtensorMapFloatOOBfill);

static void mk2d(PFN_tmapEncode enc, CUtensorMap* m, void* ptr,
                 uint64_t rows, uint64_t cols, uint32_t boxRows)
{
    cuuint64_t dims[2]    = {cols, rows};
    cuuint64_t strides[1] = {cols * 4};
    cuuint32_t box[2]     = {32, boxRows};
    cuuint32_t es[2]      = {1, 1};
    enc(m, CU_TENSOR_MAP_DATA_TYPE_FLOAT32, 2, ptr, dims, strides, box, es,
        CU_TENSOR_MAP_INTERLEAVE_NONE, CU_TENSOR_MAP_SWIZZLE_128B,
        CU_TENSOR_MAP_L2_PROMOTION_L2_128B, CU_TENSOR_MAP_FLOAT_OOB_FILL_NONE);
}

// ============================================================================
// Launch sequence (graph-capturable)
// ============================================================================
extern "C" void kernel_launch(void* const* d_in, const int* in_sizes, int n_in,
                              void* d_out, int out_size)
{
    const float* tokens = (const float*)d_in[0];
    const float* Wq = (const float*)d_in[1];
    const float* bq = (const float*)d_in[2];
    const float* Wk = (const float*)d_in[3];
    const float* bk = (const float*)d_in[4];
    const float* Wv = (const float*)d_in[5];
    const float* bv = (const float*)d_in[6];
    const float* ds = (const float*)d_in[7];
    const float* W1 = (const float*)d_in[8];
    const float* b1 = (const float*)d_in[9];
    const float* W2 = (const float*)d_in[10];
    const float* b2 = (const float*)d_in[11];
    const float* g1 = (const float*)d_in[12];
    const float* be1 = (const float*)d_in[13];
    const float* g2 = (const float*)d_in[14];
    const float* be2 = (const float*)d_in[15];
    float* out = (float*)d_out;

    float *q, *k, *v, *attn, *x, *y, *h, *s, *tokr, *wqkvT, *w1T, *w2T;
    cudaGetSymbolAddress((void**)&q, g_q);
    cudaGetSymbolAddress((void**)&k, g_k);
    cudaGetSymbolAddress((void**)&v, g_v);
    cudaGetSymbolAddress((void**)&attn, g_attn);
    cudaGetSymbolAddress((void**)&x, g_x);
    cudaGetSymbolAddress((void**)&y, g_y);
    cudaGetSymbolAddress((void**)&h, g_h);
    cudaGetSymbolAddress((void**)&s, g_s);
    cudaGetSymbolAddress((void**)&tokr, g_tokr);
    cudaGetSymbolAddress((void**)&wqkvT, g_wqkvT);
    cudaGetSymbolAddress((void**)&w1T, g_w1T);
    cudaGetSymbolAddress((void**)&w2T, g_w2T);

    // driver entry point for tensormap encode (host-only, capture-safe)
    PFN_tmapEncode enc = nullptr;
    {
        void* p = nullptr;
        cudaDriverEntryPointQueryResult st;
        cudaGetDriverEntryPoint("cuTensorMapEncodeTiled", &p, cudaEnableDefault, &st);
        enc = (PFN_tmapEncode)p;
    }

    CUtensorMap tmTok, tmWqkv, tmQ, tmK, tmX, tmW1, tmH, tmW2;
    mk2d(enc, &tmTok,  tokr,  NTOK,        D_MODEL, 256);
    mk2d(enc, &tmWqkv, wqkvT, 3 * D_MODEL, D_MODEL, 128);
    mk2d(enc, &tmQ,    q,     NTOK,        D_MODEL, 256);
    mk2d(enc, &tmK,    k,     NTOK,        D_MODEL, 128);
    mk2d(enc, &tmX,    x,     NTOK,        D_MODEL, 256);
    mk2d(enc, &tmW1,   w1T,   HDIM,        D_MODEL, 128);
    mk2d(enc, &tmH,    h,     NTOK,        HDIM,    256);
    mk2d(enc, &tmW2,   w2T,   D_MODEL,     HDIM,    128);

    cudaFuncSetAttribute(gemm_tma<0, 1, 0, 1>, cudaFuncAttributeMaxDynamicSharedMemorySize, TSMEM_BYTES);
    cudaFuncSetAttribute(gemm_tma<0, 0, 1, 0>, cudaFuncAttributeMaxDynamicSharedMemorySize, TSMEM_BYTES);
    cudaFuncSetAttribute(gemm_tma<1, 1, 0, 0>, cudaFuncAttributeMaxDynamicSharedMemorySize, TSMEM_BYTES);
    cudaFuncSetAttribute(gemm_tma<0, 0, 0, 0>, cudaFuncAttributeMaxDynamicSharedMemorySize, TSMEM_BYTES);
    cudaFuncSetAttribute(gemm_tc<0, 1, 0, 0>,  cudaFuncAttributeMaxDynamicSharedMemorySize, PV_SMEM_BYTES);

    // 0: round tokens to tf32
    round_kernel<<<(NTOK * D_MODEL / 4 + 255) / 256, 256>>>(tokens, tokr, NTOK * D_MODEL / 4);

    // 1: transpose+round all weights
    transpose_all<<<dim3(64, 64, 5), 256>>>(Wq, Wk, Wv, W1, W2, wqkvT, w1T, w2T);

    // 2: QKV (TMA): C_z = tokr @ Wz^T + bz, tf32-rounded
    gemm_tma<0, 1, 0, 1><<<dim3(D_MODEL / TBN, NTOK / TBM, 3), 256, TSMEM_BYTES>>>(
        tmTok, tmWqkv, bq, bk, bv, q, k, v, D_MODEL, D_MODEL, 0, D_MODEL, 0);

    // 3: scores (TMA, causal-skip): S = Q @ K^T per batch
    gemm_tma<0, 0, 1, 0><<<dim3(TSEQ / TBN, TSEQ / TBM, NB), 256, TSMEM_BYTES>>>(
        tmQ, tmK, nullptr, nullptr, nullptr, s, nullptr, nullptr,
        TSEQ, D_MODEL, TSEQ, TSEQ, (long)TSEQ * TSEQ);

    // 4: softmax
    softmax_kernel<<<dim3(TSEQ, NB), 256>>>(s, ds);

    // 5: PV (old path): attn = P @ V, K clamped causal
    gemm_tc<0, 1, 0, 0><<<dim3(D_MODEL / 128, TSEQ / 128, NB), 128, PV_SMEM_BYTES>>>(
        s, v, nullptr, attn, TSEQ, D_MODEL, TSEQ,
        (long)TSEQ * TSEQ, (long)TSEQ * D_MODEL, (long)TSEQ * D_MODEL);

    // 6: x = LN(tokens + attn), tf32-rounded
    ln_kernel<1><<<NTOK, 128>>>(tokens, attn, g1, be1, x);

    // 7: FFN1 (TMA): h = relu(x @ W1^T' + b1), tf32-rounded
    gemm_tma<1, 1, 0, 0><<<dim3(HDIM / TBN, NTOK / TBM, 1), 256, TSMEM_BYTES>>>(
        tmX, tmW1, b1, nullptr, nullptr, h, nullptr, nullptr,
        HDIM, D_MODEL, 0, 0, 0);

    // 8: FFN2 (TMA): y = h @ W2^T' + b2
    gemm_tma<0, 0, 0, 0><<<dim3(D_MODEL / TBN, NTOK / TBM, 1), 256, TSMEM_BYTES>>>(
        tmH, tmW2, b2, nullptr, nullptr, y, nullptr, nullptr,
        D_MODEL, HDIM, 0, 0, 0);

    // 9: z = LN(y + x)
    ln_kernel<0><<<NTOK, 128>>>(y, x, g2, be2, out);
}

// round 11
// speedup vs baseline: 1.0758x; 1.0079x over previous
#include <cuda_runtime.h>
#include <cuda.h>
#include <math.h>
#include <stdint.h>

// Problem constants
#define D_MODEL 512
#define HDIM    2048
#define TSEQ    4096
#define NB      2
#define NTOK    (NB * TSEQ)  // 8192

// ---- TMA kernel config ----
#define TBM 256
#define TBN 128
#define TBK 32
#define A_STAGE_B 32768            // 256 rows * 128 B
#define B_STAGE_B 16384            // 128 rows * 128 B
#define STAGE_B   (A_STAGE_B + B_STAGE_B)   // 49152
#define NST 3
#define TSMEM_BYTES (NST * STAGE_B + 128)   // 147456 + mbarriers

// -------- static scratch (allocation-free per harness rules) --------
__device__ float g_q[(size_t)NTOK * D_MODEL];
__device__ float g_k[(size_t)NTOK * D_MODEL];
__device__ float g_v[(size_t)NTOK * D_MODEL];
__device__ float g_vT[(size_t)NB * D_MODEL * TSEQ];   // [b][d][s]
__device__ float g_attn[(size_t)NTOK * D_MODEL];
__device__ float g_x[(size_t)NTOK * D_MODEL];
__device__ float g_y[(size_t)NTOK * D_MODEL];
__device__ float g_h[(size_t)NTOK * HDIM];
__device__ float g_s[(size_t)NB * TSEQ * TSEQ];
__device__ float g_tokr[(size_t)NTOK * D_MODEL];
// transposed tf32-rounded weights ([N,K] layouts)
__device__ float g_wqkvT[(size_t)3 * D_MODEL * D_MODEL];
__device__ float g_w1T[(size_t)HDIM * D_MODEL];
__device__ float g_w2T[(size_t)D_MODEL * HDIM];

// ---------------------------------------------------------------------------
// helpers
// ---------------------------------------------------------------------------
__device__ __forceinline__ float to_tf32(float x) {
    uint32_t u;
    asm("cvt.rna.tf32.f32 %0, %1;" : "=r"(u) : "f"(x));
    return __uint_as_float(u);
}

__device__ __forceinline__ void mma_tf32(float c[4], const float a[4], const float b[2]) {
    asm volatile(
        "mma.sync.aligned.m16n8k8.row.col.f32.tf32.tf32.f32 "
        "{%0,%1,%2,%3}, {%4,%5,%6,%7}, {%8,%9}, {%0,%1,%2,%3};"
        : "+f"(c[0]), "+f"(c[1]), "+f"(c[2]), "+f"(c[3])
        : "r"(__float_as_uint(a[0])), "r"(__float_as_uint(a[1])),
          "r"(__float_as_uint(a[2])), "r"(__float_as_uint(a[3])),
          "r"(__float_as_uint(b[0])), "r"(__float_as_uint(b[1])));
}

__device__ __forceinline__ uint32_t smem_u32(const void* p) {
    return (uint32_t)__cvta_generic_to_shared(p);
}

// ---- mbarrier / TMA primitives ----
__device__ __forceinline__ void mbar_init(uint32_t a, uint32_t cnt) {
    asm volatile("mbarrier.init.shared.b64 [%0], %1;" :: "r"(a), "r"(cnt) : "memory");
}
__device__ __forceinline__ void mbar_expect(uint32_t a, uint32_t tx) {
    asm volatile("mbarrier.arrive.expect_tx.shared.b64 _, [%0], %1;" :: "r"(a), "r"(tx) : "memory");
}
__device__ __forceinline__ void mbar_wait(uint32_t a, int parity) {
    asm volatile(
        "{\n\t"
        ".reg .pred P1;\n\t"
        "WAIT_LOOP_%=:\n\t"
        "mbarrier.try_wait.parity.acquire.cta.shared::cta.b64 P1, [%0], %1, 0x989680;\n\t"
        "@P1 bra.uni WAIT_DONE_%=;\n\t"
        "bra.uni WAIT_LOOP_%=;\n\t"
        "WAIT_DONE_%=:\n\t"
        "}"
        :: "r"(a), "r"(parity) : "memory");
}
__device__ __forceinline__ void tma2d(uint32_t dst, const void* map, int cx, int cy, uint32_t bar) {
    asm volatile(
        "cp.async.bulk.tensor.2d.shared::cta.global.tile.mbarrier::complete_tx::bytes "
        "[%0], [%1, {%2, %3}], [%4];"
        :: "r"(dst), "l"(map), "r"(cx), "r"(cy), "r"(bar) : "memory");
}

// SW128-swizzled fp32 element in a [rows][32] tile with 128B rows
__device__ __forceinline__ float SWF(const char* base, int row, int col) {
    int off = row * 128 + col * 4;
    off ^= (off >> 3) & 0x70;
    return *(const float*)(base + off);
}

// ============================================================================
// TMA-fed tf32 GEMM: C[TBM x TBN] per CTA, 256 threads, 8 warps of 64x64.
// 3-stage pipeline, prefetch issued BEFORE compute (post-barrier, race-free).
// A map rows-major [Mtot,K], box (32,256). B map [Ntot,K], box (32,128);
// computes C = A @ B^T.
//   CAUSAL=1: skip score tiles fully above diagonal;
//   MULTI=1:  blockIdx.z selects out/bias (QKV); else out = o0 + z*ozs;
//   KCAU=1:   K clamped to m0+TBM (causal P@V).
// ============================================================================
template <int RELU, int ROUND, int CAUSAL, int MULTI, int KCAU>
__global__ __launch_bounds__(256, 1) void gemm_tma(
    const __grid_constant__ CUtensorMap tmA,
    const __grid_constant__ CUtensorMap tmB,
    const float* __restrict__ b0, const float* __restrict__ b1, const float* __restrict__ b2,
    float* __restrict__ o0, float* __restrict__ o1, float* __restrict__ o2,
    int Cstride, int K, int za, int zb, long ozs)
{
    if (CAUSAL && (int)blockIdx.x > 2 * (int)blockIdx.y + 1) return;

    extern __shared__ __align__(1024) char smem[];
    const int tid = threadIdx.x;
    const int z   = blockIdx.z;
    const int m0  = blockIdx.y * TBM;
    const int n0  = blockIdx.x * TBN;
    const int ya  = m0 + z * za;
    const int yb  = n0 + z * zb;
    const uint32_t sbase = smem_u32(smem);
    const uint32_t barb = sbase + NST * STAGE_B;
    const int Keff = KCAU ? min(K, m0 + TBM) : K;
    const int NS = Keff / TBK;

    if (tid == 0) {
        mbar_init(barb + 0, 1);
        mbar_init(barb + 8, 1);
        mbar_init(barb + 16, 1);
    }
    __syncthreads();
    if (tid == 0) {
        mbar_expect(barb + 0, STAGE_B);
        tma2d(sbase, &tmA, 0, ya, barb + 0);
        tma2d(sbase + A_STAGE_B, &tmB, 0, yb, barb + 0);
        mbar_expect(barb + 8, STAGE_B);
        tma2d(sbase + STAGE_B, &tmA, TBK, ya, barb + 8);
        tma2d(sbase + STAGE_B + A_STAGE_B, &tmB, TBK, yb, barb + 8);
    }

    const int lane = tid & 31;
    const int gid  = lane >> 2;
    const int tg   = lane & 3;
    const int warp = tid >> 5;           // 0..7
    const int mw   = (warp >> 1) * 64;
    const int nw   = (warp & 1) * 64;

    float acc[4][8][4] = {};

    for (int s = 0; s < NS; s++) {
        const int slot = s % NST;
        mbar_wait(barb + 8 * slot, (s / NST) & 1);
        __syncthreads();  // all warps finished stage s-1 -> slot (s+2)%NST reusable
        if (tid == 0 && s + 2 < NS) {
            const int ps = (s + 2) % NST;
            mbar_expect(barb + 8 * ps, STAGE_B);
            tma2d(sbase + ps * STAGE_B, &tmA, (s + 2) * TBK, ya, barb + 8 * ps);
            tma2d(sbase + ps * STAGE_B + A_STAGE_B, &tmB, (s + 2) * TBK, yb, barb + 8 * ps);
        }

        const char* As = smem + slot * STAGE_B;
        const char* Bs = As + A_STAGE_B;

#pragma unroll
        for (int ks = 0; ks < 4; ks++) {
            const int kk = ks * 8;
            float a[4][4];
#pragma unroll
            for (int i = 0; i < 4; i++) {
                int r = mw + i * 16 + gid;
                a[i][0] = SWF(As, r,     kk + tg);
                a[i][1] = SWF(As, r + 8, kk + tg);
                a[i][2] = SWF(As, r,     kk + tg + 4);
                a[i][3] = SWF(As, r + 8, kk + tg + 4);
            }
            float bb[8][2];
#pragma unroll
            for (int j = 0; j < 8; j++) {
                int r = nw + j * 8 + gid;
                bb[j][0] = SWF(Bs, r, kk + tg);
                bb[j][1] = SWF(Bs, r, kk + tg + 4);
            }
#pragma unroll
            for (int i = 0; i < 4; i++)
#pragma unroll
                for (int j = 0; j < 8; j++) mma_tf32(acc[i][j], a[i], bb[j]);
        }
    }

    // ---- epilogue ----
    float* C;
    const float* bias;
    if (MULTI) {
        C    = (z == 0) ? o0 : (z == 1) ? o1 : o2;
        bias = (z == 0) ? b0 : (z == 1) ? b1 : b2;
    } else {
        C    = o0 + (size_t)z * ozs;
        bias = b0;
    }
#pragma unroll
    for (int i = 0; i < 4; i++) {
        int m = m0 + mw + i * 16 + gid;
#pragma unroll
        for (int j = 0; j < 8; j++) {
            int n = n0 + nw + j * 8 + tg * 2;
            float2 lo = make_float2(acc[i][j][0], acc[i][j][1]);
            float2 hi = make_float2(acc[i][j][2], acc[i][j][3]);
            if (bias) {
                float u0 = bias[n], u1 = bias[n + 1];
                lo.x += u0; lo.y += u1; hi.x += u0; hi.y += u1;
            }
            if (RELU) {
                lo.x = fmaxf(lo.x, 0.f); lo.y = fmaxf(lo.y, 0.f);
                hi.x = fmaxf(hi.x, 0.f); hi.y = fmaxf(hi.y, 0.f);
            }
            if (ROUND) {
                lo.x = to_tf32(lo.x); lo.y = to_tf32(lo.y);
                hi.x = to_tf32(hi.x); hi.y = to_tf32(hi.y);
            }
            *(float2*)(C + (size_t)m * Cstride + n) = lo;
            *(float2*)(C + (size_t)(m + 8) * Cstride + n) = hi;
        }
    }
}

// ============================================================================
// Pre-pass kernels
// ============================================================================
__global__ __launch_bounds__(256) void round_kernel(
    const float* __restrict__ in, float* __restrict__ out, int n4)
{
    int i = blockIdx.x * 256 + threadIdx.x;
    if (i < n4) {
        float4 v = ((const float4*)in)[i];
        v.x = to_tf32(v.x); v.y = to_tf32(v.y);
        v.z = to_tf32(v.z); v.w = to_tf32(v.w);
        ((float4*)out)[i] = v;
    }
}

// Transpose + tf32-round all weights. z: 0..2=Wq/Wk/Wv, 3=W1, 4=W2.
__global__ __launch_bounds__(256) void transpose_all(
    const float* __restrict__ Wq, const float* __restrict__ Wk, const float* __restrict__ Wv,
    const float* __restrict__ W1, const float* __restrict__ W2,
    float* __restrict__ wqkvT, float* __restrict__ w1T, float* __restrict__ w2T)
{
    __shared__ float t[32][33];
    const int z = blockIdx.z;
    const float* in;
    float* out;
    int R, C;
    if (z < 3)      { in = z == 0 ? Wq : z == 1 ? Wk : Wv; out = wqkvT + (size_t)z * D_MODEL * D_MODEL; R = 512; C = 512; }
    else if (z == 3){ in = W1; out = w1T; R = 512; C = 2048; }
    else            { in = W2; out = w2T; R = 2048; C = 512; }
    const int cb = blockIdx.x * 32, rb = blockIdx.y * 32;
    if (cb >= C || rb >= R) return;
    const int tx = threadIdx.x & 31, ty = threadIdx.x >> 5;
    for (int i = ty; i < 32; i += 8) t[i][tx] = in[(size_t)(rb + i) * C + cb + tx];
    __syncthreads();
    for (int i = ty; i < 32; i += 8) out[(size_t)(cb + i) * R + rb + tx] = to_tf32(t[tx][i]);
}

// Per-batch V transpose: vT[b][d][s] = v[b*TSEQ + s][d] (v already tf32).
__global__ __launch_bounds__(256) void vtrans_kernel(
    const float* __restrict__ v, float* __restrict__ vT)
{
    __shared__ float t[32][33];
    const int b  = blockIdx.z;
    const int sb = blockIdx.x * 32;
    const int db = blockIdx.y * 32;
    const float* in = v + (size_t)b * TSEQ * D_MODEL;
    float* out = vT + (size_t)b * D_MODEL * TSEQ;
    const int tx = threadIdx.x & 31, ty = threadIdx.x >> 5;
    for (int i = ty; i < 32; i += 8) t[i][tx] = in[(size_t)(sb + i) * D_MODEL + db + tx];
    __syncthreads();
    for (int i = ty; i < 32; i += 8) out[(size_t)(db + i) * TSEQ + sb + tx] = t[tx][i];
}

// ---------------------------------------------------------------------------
// FMA-only exp (input <= 0 after max-subtract; clamped).
// ---------------------------------------------------------------------------
__device__ __forceinline__ float fast_exp(float x) {
    x = fmaxf(x, -87.0f);
    float z = x * 1.4426950408889634f;
    float n = rintf(z);
    float t = z - n;
    float p = 1.5403530e-4f;
    p = fmaf(p, t, 1.3333558e-3f);
    p = fmaf(p, t, 9.6181291e-3f);
    p = fmaf(p, t, 5.5504109e-2f);
    p = fmaf(p, t, 2.4022651e-1f);
    p = fmaf(p, t, 6.9314718e-1f);
    p = fmaf(p, t, 1.0f);
    int e = (int)n;
    return p * __int_as_float((e + 127) << 23);
}

// ============================================================================
// Row softmax (in-place, register-resident). tf32-rounded output.
// Zero-fill now extends to the next 256 boundary (PV reads K up to m0+256).
// ============================================================================
__global__ __launch_bounds__(256) void softmax_kernel(
    float* __restrict__ S, const float* __restrict__ ds_ptr)
{
    __shared__ float red[8];

    const int t = blockIdx.x;
    const int b = blockIdx.y;
    const int tid = threadIdx.x;
    const int lane = tid & 31;
    const int wid  = tid >> 5;
    float* row = S + ((size_t)b * TSEQ + t) * TSEQ;

    const float ds = *ds_ptr;
    const float scale = rsqrtf((float)D_MODEL);
    const int len = t + 1;
    const int limit = ((t >> 8) + 1) << 8;  // next 256 boundary (PV TBM=256)

    float v[16];
    float mx = -1e30f;
#pragma unroll
    for (int it = 0; it < 16; it++) {
        int s = tid + it * 256;
        float val = -1e30f;
        if (s < len) val = (row[s] - ds * (float)(t - s)) * scale;
        v[it] = val;
        mx = fmaxf(mx, val);
    }
#pragma unroll
    for (int o = 16; o; o >>= 1) mx = fmaxf(mx, __shfl_xor_sync(0xffffffffu, mx, o));
    if (lane == 0) red[wid] = mx;
    __syncthreads();
    float mall = -1e30f;
#pragma unroll
    for (int w = 0; w < 8; w++) mall = fmaxf(mall, red[w]);
    __syncthreads();

    float sum = 0.f;
#pragma unroll
    for (int it = 0; it < 16; it++) {
        int s = tid + it * 256;
        float e = (s < len) ? fast_exp(v[it] - mall) : 0.f;
        v[it] = e;
        sum += e;
    }
#pragma unroll
    for (int o = 16; o; o >>= 1) sum += __shfl_xor_sync(0xffffffffu, sum, o);
    if (lane == 0) red[wid] = sum;
    __syncthreads();
    float sall = 0.f;
#pragma unroll
    for (int w = 0; w < 8; w++) sall += red[w];
    const float inv = 1.0f / sall;

#pragma unroll
    for (int it = 0; it < 16; it++) {
        int s = tid + it * 256;
        if (s < len)        row[s] = to_tf32(v[it] * inv);
        else if (s < limit) row[s] = 0.f;
    }
}

// ============================================================================
// LayerNorm: out = LN(A + R) * gamma + beta.  ROUND rounds to tf32.
// ============================================================================
template <int ROUND>
__global__ __launch_bounds__(128) void ln_kernel(
    const float* __restrict__ A, const float* __restrict__ R,
    const float* __restrict__ gamma, const float* __restrict__ beta,
    float* __restrict__ out)
{
    __shared__ float sh[4];
    const int row = blockIdx.x;
    const int tid = threadIdx.x;
    const size_t base = (size_t)row * D_MODEL + tid * 4;

    float4 a = *(const float4*)(A + base);
    float4 r = *(const float4*)(R + base);
    float x0 = a.x + r.x, x1 = a.y + r.y, x2 = a.z + r.z, x3 = a.w + r.w;

    float s = x0 + x1 + x2 + x3;
    for (int o = 16; o; o >>= 1) s += __shfl_xor_sync(0xffffffffu, s, o);
    if ((tid & 31) == 0) sh[tid >> 5] = s;
    __syncthreads();
    const float mean = (sh[0] + sh[1] + sh[2] + sh[3]) * (1.0f / D_MODEL);
    __syncthreads();

    float d0 = x0 - mean, d1 = x1 - mean, d2 = x2 - mean, d3 = x3 - mean;
    float sq = d0 * d0 + d1 * d1 + d2 * d2 + d3 * d3;
    for (int o = 16; o; o >>= 1) sq += __shfl_xor_sync(0xffffffffu, sq, o);
    if ((tid & 31) == 0) sh[tid >> 5] = sq;
    __syncthreads();
    const float var = (sh[0] + sh[1] + sh[2] + sh[3]) * (1.0f / D_MODEL);
    const float rstd = rsqrtf(var + 1e-5f);

    float4 g  = *(const float4*)(gamma + tid * 4);
    float4 be = *(const float4*)(beta + tid * 4);
    float4 o4;
    o4.x = d0 * rstd * g.x + be.x;
    o4.y = d1 * rstd * g.y + be.y;
    o4.z = d2 * rstd * g.z + be.z;
    o4.w = d3 * rstd * g.w + be.w;
    if (ROUND) {
        o4.x = to_tf32(o4.x); o4.y = to_tf32(o4.y);
        o4.z = to_tf32(o4.z); o4.w = to_tf32(o4.w);
    }
    *(float4*)(out + base) = o4;
}

// ============================================================================
// Host: tensormap construction via driver entry point (no -lcuda needed)
// ============================================================================
typedef CUresult (*PFN_tmapEncode)(
    CUtensorMap*, CUtensorMapDataType, cuuint32_t, void*,
    const cuuint64_t*, const cuuint64_t*, const cuuint32_t*, const cuuint32_t*,
    CUtensorMapInterleave, CUtensorMapSwizzle, CUtensorMapL2promotion,
    CUtensorMapFloatOOBfill);

static void mk2d(PFN_tmapEncode enc, CUtensorMap* m, void* ptr,
                 uint64_t rows, uint64_t cols, uint32_t boxRows)
{
    cuuint64_t dims[2]    = {cols, rows};
    cuuint64_t strides[1] = {cols * 4};
    cuuint32_t box[2]     = {32, boxRows};
    cuuint32_t es[2]      = {1, 1};
    enc(m, CU_TENSOR_MAP_DATA_TYPE_FLOAT32, 2, ptr, dims, strides, box, es,
        CU_TENSOR_MAP_INTERLEAVE_NONE, CU_TENSOR_MAP_SWIZZLE_128B,
        CU_TENSOR_MAP_L2_PROMOTION_L2_128B, CU_TENSOR_MAP_FLOAT_OOB_FILL_NONE);
}

// ============================================================================
// Launch sequence (graph-capturable)
// ============================================================================
extern "C" void kernel_launch(void* const* d_in, const int* in_sizes, int n_in,
                              void* d_out, int out_size)
{
    const float* tokens = (const float*)d_in[0];
    const float* Wq = (const float*)d_in[1];
    const float* bq = (const float*)d_in[2];
    const float* Wk = (const float*)d_in[3];
    const float* bk = (const float*)d_in[4];
    const float* Wv = (const float*)d_in[5];
    const float* bv = (const float*)d_in[6];
    const float* ds = (const float*)d_in[7];
    const float* W1 = (const float*)d_in[8];
    const float* b1 = (const float*)d_in[9];
    const float* W2 = (const float*)d_in[10];
    const float* b2 = (const float*)d_in[11];
    const float* g1 = (const float*)d_in[12];
    const float* be1 = (const float*)d_in[13];
    const float* g2 = (const float*)d_in[14];
    const float* be2 = (const float*)d_in[15];
    float* out = (float*)d_out;

    float *q, *k, *v, *vT, *attn, *x, *y, *h, *s, *tokr, *wqkvT, *w1T, *w2T;
    cudaGetSymbolAddress((void**)&q, g_q);
    cudaGetSymbolAddress((void**)&k, g_k);
    cudaGetSymbolAddress((void**)&v, g_v);
    cudaGetSymbolAddress((void**)&vT, g_vT);
    cudaGetSymbolAddress((void**)&attn, g_attn);
    cudaGetSymbolAddress((void**)&x, g_x);
    cudaGetSymbolAddress((void**)&y, g_y);
    cudaGetSymbolAddress((void**)&h, g_h);
    cudaGetSymbolAddress((void**)&s, g_s);
    cudaGetSymbolAddress((void**)&tokr, g_tokr);
    cudaGetSymbolAddress((void**)&wqkvT, g_wqkvT);
    cudaGetSymbolAddress((void**)&w1T, g_w1T);
    cudaGetSymbolAddress((void**)&w2T, g_w2T);

    PFN_tmapEncode enc = nullptr;
    {
        void* p = nullptr;
        cudaDriverEntryPointQueryResult st;
        cudaGetDriverEntryPoint("cuTensorMapEncodeTiled", &p, cudaEnableDefault, &st);
        enc = (PFN_tmapEncode)p;
    }

    CUtensorMap tmTok, tmWqkv, tmQ, tmK, tmX, tmW1, tmH, tmW2, tmP, tmV;
    mk2d(enc, &tmTok,  tokr,  NTOK,           D_MODEL, 256);
    mk2d(enc, &tmWqkv, wqkvT, 3 * D_MODEL,    D_MODEL, 128);
    mk2d(enc, &tmQ,    q,     NTOK,           D_MODEL, 256);
    mk2d(enc, &tmK,    k,     NTOK,           D_MODEL, 128);
    mk2d(enc, &tmX,    x,     NTOK,           D_MODEL, 256);
    mk2d(enc, &tmW1,   w1T,   HDIM,           D_MODEL, 128);
    mk2d(enc, &tmH,    h,     NTOK,           HDIM,    256);
    mk2d(enc, &tmW2,   w2T,   D_MODEL,        HDIM,    128);
    mk2d(enc, &tmP,    s,     (uint64_t)NB * TSEQ, TSEQ, 256);
    mk2d(enc, &tmV,    vT,    (uint64_t)NB * D_MODEL, TSEQ, 128);

    cudaFuncSetAttribute(gemm_tma<0, 1, 0, 1, 0>, cudaFuncAttributeMaxDynamicSharedMemorySize, TSMEM_BYTES);
    cudaFuncSetAttribute(gemm_tma<0, 0, 1, 0, 0>, cudaFuncAttributeMaxDynamicSharedMemorySize, TSMEM_BYTES);
    cudaFuncSetAttribute(gemm_tma<0, 0, 0, 0, 1>, cudaFuncAttributeMaxDynamicSharedMemorySize, TSMEM_BYTES);
    cudaFuncSetAttribute(gemm_tma<1, 1, 0, 0, 0>, cudaFuncAttributeMaxDynamicSharedMemorySize, TSMEM_BYTES);
    cudaFuncSetAttribute(gemm_tma<0, 0, 0, 0, 0>, cudaFuncAttributeMaxDynamicSharedMemorySize, TSMEM_BYTES);

    // 0: round tokens to tf32
    round_kernel<<<(NTOK * D_MODEL / 4 + 255) / 256, 256>>>(tokens, tokr, NTOK * D_MODEL / 4);

    // 1: transpose+round all weights
    transpose_all<<<dim3(64, 64, 5), 256>>>(Wq, Wk, Wv, W1, W2, wqkvT, w1T, w2T);

    // 2: QKV (TMA): C_z = tokr @ Wz^T + bz, tf32-rounded
    gemm_tma<0, 1, 0, 1, 0><<<dim3(D_MODEL / TBN, NTOK / TBM, 3), 256, TSMEM_BYTES>>>(
        tmTok, tmWqkv, bq, bk, bv, q, k, v, D_MODEL, D_MODEL, 0, D_MODEL, 0);

    // 2b: vT[b][d][s] = v
    vtrans_kernel<<<dim3(TSEQ / 32, D_MODEL / 32, NB), 256>>>(v, vT);

    // 3: scores (TMA, causal-skip): S = Q @ K^T per batch
    gemm_tma<0, 0, 1, 0, 0><<<dim3(TSEQ / TBN, TSEQ / TBM, NB), 256, TSMEM_BYTES>>>(
        tmQ, tmK, nullptr, nullptr, nullptr, s, nullptr, nullptr,
        TSEQ, D_MODEL, TSEQ, TSEQ, (long)TSEQ * TSEQ);

    // 4: softmax (zero-fill to 256 boundary)
    softmax_kernel<<<dim3(TSEQ, NB), 256>>>(s, ds);

    // 5: PV (TMA, K clamped to m0+256): attn = P @ vT^T
    gemm_tma<0, 0, 0, 0, 1><<<dim3(D_MODEL / TBN, TSEQ / TBM, NB), 256, TSMEM_BYTES>>>(
        tmP, tmV, nullptr, nullptr, nullptr, attn, nullptr, nullptr,
        D_MODEL, TSEQ, TSEQ, D_MODEL, (long)TSEQ * D_MODEL);

    // 6: x = LN(tokens + attn), tf32-rounded
    ln_kernel<1><<<NTOK, 128>>>(tokens, attn, g1, be1, x);

    // 7: FFN1 (TMA): h = relu(x @ W1^T' + b1), tf32-rounded
    gemm_tma<1, 1, 0, 0, 0><<<dim3(HDIM / TBN, NTOK / TBM, 1), 256, TSMEM_BYTES>>>(
        tmX, tmW1, b1, nullptr, nullptr, h, nullptr, nullptr,
        HDIM, D_MODEL, 0, 0, 0);

    // 8: FFN2 (TMA): y = h @ W2^T' + b2
    gemm_tma<0, 0, 0, 0, 0><<<dim3(D_MODEL / TBN, NTOK / TBM, 1), 256, TSMEM_BYTES>>>(
        tmH, tmW2, b2, nullptr, nullptr, y, nullptr, nullptr,
        D_MODEL, HDIM, 0, 0, 0);

    // 9: z = LN(y + x)
    ln_kernel<0><<<NTOK, 128>>>(y, x, g2, be2, out);
}

// round 14
// speedup vs baseline: 1.2153x; 1.1296x over previous
#include <cuda_runtime.h>
#include <cuda.h>
#include <math.h>
#include <stdint.h>

// Problem constants
#define D_MODEL 512
#define HDIM    2048
#define TSEQ    4096
#define NB      2
#define NTOK    (NB * TSEQ)  // 8192

// ---- TMA kernel config: 128x128 tile, 128 threads, 2 CTAs/SM ----
#define TBM 128
#define TBN 128
#define TBK 32
#define A_STAGE_B 16384            // 128 rows * 128 B
#define B_STAGE_B 16384
#define STAGE_B   (A_STAGE_B + B_STAGE_B)   // 32768
#define NST 3
#define TSMEM_BYTES (NST * STAGE_B + 128)   // 98432

// -------- static scratch (allocation-free per harness rules) --------
__device__ float g_q[(size_t)NTOK * D_MODEL];
__device__ float g_k[(size_t)NTOK * D_MODEL];
__device__ float g_v[(size_t)NTOK * D_MODEL];
__device__ float g_vT[(size_t)NB * D_MODEL * TSEQ];   // [b][d][s]
__device__ float g_attn[(size_t)NTOK * D_MODEL];
__device__ float g_x[(size_t)NTOK * D_MODEL];
__device__ float g_y[(size_t)NTOK * D_MODEL];
__device__ float g_h[(size_t)NTOK * HDIM];
__device__ float g_s[(size_t)NB * TSEQ * TSEQ];
__device__ float g_tokr[(size_t)NTOK * D_MODEL];
__device__ float g_wqkvT[(size_t)3 * D_MODEL * D_MODEL];
__device__ float g_w1T[(size_t)HDIM * D_MODEL];
__device__ float g_w2T[(size_t)D_MODEL * HDIM];

// ---------------------------------------------------------------------------
// helpers
// ---------------------------------------------------------------------------
__device__ __forceinline__ float to_tf32(float x) {
    uint32_t u;
    asm("cvt.rna.tf32.f32 %0, %1;" : "=r"(u) : "f"(x));
    return __uint_as_float(u);
}

__device__ __forceinline__ void mma_tf32(float c[4], const float a[4], const float b[2]) {
    asm volatile(
        "mma.sync.aligned.m16n8k8.row.col.f32.tf32.tf32.f32 "
        "{%0,%1,%2,%3}, {%4,%5,%6,%7}, {%8,%9}, {%0,%1,%2,%3};"
        : "+f"(c[0]), "+f"(c[1]), "+f"(c[2]), "+f"(c[3])
        : "r"(__float_as_uint(a[0])), "r"(__float_as_uint(a[1])),
          "r"(__float_as_uint(a[2])), "r"(__float_as_uint(a[3])),
          "r"(__float_as_uint(b[0])), "r"(__float_as_uint(b[1])));
}

__device__ __forceinline__ uint32_t smem_u32(const void* p) {
    return (uint32_t)__cvta_generic_to_shared(p);
}

// ---- mbarrier / TMA primitives ----
__device__ __forceinline__ void mbar_init(uint32_t a, uint32_t cnt) {
    asm volatile("mbarrier.init.shared.b64 [%0], %1;" :: "r"(a), "r"(cnt) : "memory");
}
__device__ __forceinline__ void mbar_expect(uint32_t a, uint32_t tx) {
    asm volatile("mbarrier.arrive.expect_tx.shared.b64 _, [%0], %1;" :: "r"(a), "r"(tx) : "memory");
}
__device__ __forceinline__ void mbar_wait(uint32_t a, int parity) {
    asm volatile(
        "{\n\t"
        ".reg .pred P1;\n\t"
        "WAIT_LOOP_%=:\n\t"
        "mbarrier.try_wait.parity.acquire.cta.shared::cta.b64 P1, [%0], %1, 0x989680;\n\t"
        "@P1 bra.uni WAIT_DONE_%=;\n\t"
        "bra.uni WAIT_LOOP_%=;\n\t"
        "WAIT_DONE_%=:\n\t"
        "}"
        :: "r"(a), "r"(parity) : "memory");
}
__device__ __forceinline__ void tma2d(uint32_t dst, const void* map, int cx, int cy, uint32_t bar) {
    asm volatile(
        "cp.async.bulk.tensor.2d.shared::cta.global.tile.mbarrier::complete_tx::bytes "
        "[%0], [%1, {%2, %3}], [%4];"
        :: "r"(dst), "l"(map), "r"(cx), "r"(cy), "r"(bar) : "memory");
}

// SW128-swizzled fp32 element in a [rows][32] tile with 128B rows
__device__ __forceinline__ float SWF(const char* base, int row, int col) {
    int off = row * 128 + col * 4;
    off ^= (off >> 3) & 0x70;
    return *(const float*)(base + off);
}

// ============================================================================
// TMA-fed tf32 GEMM: C[128 x 128] per CTA, 128 threads, 4 warps of 64x64.
// 3-stage pipeline, prefetch issued BEFORE compute. 2 CTAs/SM (96KB smem).
// A map [Mtot,K] box(32,128); B map [Ntot,K] box(32,128); C = A @ B^T.
//   CAUSAL=1: skip score tiles fully above diagonal (bx > by);
//   MULTI=1:  blockIdx.z selects out/bias (QKV); else out = o0 + z*ozs;
//   KCAU=1:   K clamped to m0+TBM (causal P@V).
// ============================================================================
template <int RELU, int ROUND, int CAUSAL, int MULTI, int KCAU>
__global__ __launch_bounds__(128, 2) void gemm_tma(
    const __grid_constant__ CUtensorMap tmA,
    const __grid_constant__ CUtensorMap tmB,
    const float* __restrict__ b0, const float* __restrict__ b1, const float* __restrict__ b2,
    float* __restrict__ o0, float* __restrict__ o1, float* __restrict__ o2,
    int Cstride, int K, int za, int zb, long ozs)
{
    if (CAUSAL && (int)blockIdx.x > (int)blockIdx.y) return;

    extern __shared__ __align__(1024) char smem[];
    const int tid = threadIdx.x;
    const int z   = blockIdx.z;
    const int m0  = blockIdx.y * TBM;
    const int n0  = blockIdx.x * TBN;
    const int ya  = m0 + z * za;
    const int yb  = n0 + z * zb;
    const uint32_t sbase = smem_u32(smem);
    const uint32_t barb = sbase + NST * STAGE_B;
    const int Keff = KCAU ? min(K, m0 + TBM) : K;
    const int NS = Keff / TBK;

    if (tid == 0) {
        mbar_init(barb + 0, 1);
        mbar_init(barb + 8, 1);
        mbar_init(barb + 16, 1);
    }
    __syncthreads();
    if (tid == 0) {
        mbar_expect(barb + 0, STAGE_B);
        tma2d(sbase, &tmA, 0, ya, barb + 0);
        tma2d(sbase + A_STAGE_B, &tmB, 0, yb, barb + 0);
        mbar_expect(barb + 8, STAGE_B);
        tma2d(sbase + STAGE_B, &tmA, TBK, ya, barb + 8);
        tma2d(sbase + STAGE_B + A_STAGE_B, &tmB, TBK, yb, barb + 8);
    }

    const int lane = tid & 31;
    const int gid  = lane >> 2;
    const int tg   = lane & 3;
    const int warp = tid >> 5;          // 0..3
    const int mw   = (warp >> 1) * 64;
    const int nw   = (warp & 1) * 64;

    float acc[4][8][4] = {};

    for (int s = 0; s < NS; s++) {
        const int slot = s % NST;
        mbar_wait(barb + 8 * slot, (s / NST) & 1);
        __syncthreads();  // all warps finished stage s-1 -> slot (s+2)%NST reusable
        if (tid == 0 && s + 2 < NS) {
            const int ps = (s + 2) % NST;
            mbar_expect(barb + 8 * ps, STAGE_B);
            tma2d(sbase + ps * STAGE_B, &tmA, (s + 2) * TBK, ya, barb + 8 * ps);
            tma2d(sbase + ps * STAGE_B + A_STAGE_B, &tmB, (s + 2) * TBK, yb, barb + 8 * ps);
        }

        const char* As = smem + slot * STAGE_B;
        const char* Bs = As + A_STAGE_B;

#pragma unroll
        for (int ks = 0; ks < 4; ks++) {
            const int kk = ks * 8;
            float a[4][4];
#pragma unroll
            for (int i = 0; i < 4; i++) {
                int r = mw + i * 16 + gid;
                a[i][0] = SWF(As, r,     kk + tg);
                a[i][1] = SWF(As, r + 8, kk + tg);
                a[i][2] = SWF(As, r,     kk + tg + 4);
                a[i][3] = SWF(As, r + 8, kk + tg + 4);
            }
            float bb[8][2];
#pragma unroll
            for (int j = 0; j < 8; j++) {
                int r = nw + j * 8 + gid;
                bb[j][0] = SWF(Bs, r, kk + tg);
                bb[j][1] = SWF(Bs, r, kk + tg + 4);
            }
#pragma unroll
            for (int i = 0; i < 4; i++)
#pragma unroll
                for (int j = 0; j < 8; j++) mma_tf32(acc[i][j], a[i], bb[j]);
        }
    }

    // ---- epilogue ----
    float* C;
    const float* bias;
    if (MULTI) {
        C    = (z == 0) ? o0 : (z == 1) ? o1 : o2;
        bias = (z == 0) ? b0 : (z == 1) ? b1 : b2;
    } else {
        C    = o0 + (size_t)z * ozs;
        bias = b0;
    }
#pragma unroll
    for (int i = 0; i < 4; i++) {
        int m = m0 + mw + i * 16 + gid;
#pragma unroll
        for (int j = 0; j < 8; j++) {
            int n = n0 + nw + j * 8 + tg * 2;
            float2 lo = make_float2(acc[i][j][0], acc[i][j][1]);
            float2 hi = make_float2(acc[i][j][2], acc[i][j][3]);
            if (bias) {
                float u0 = bias[n], u1 = bias[n + 1];
                lo.x += u0; lo.y += u1; hi.x += u0; hi.y += u1;
            }
            if (RELU) {
                lo.x = fmaxf(lo.x, 0.f); lo.y = fmaxf(lo.y, 0.f);
                hi.x = fmaxf(hi.x, 0.f); hi.y = fmaxf(hi.y, 0.f);
            }
            if (ROUND) {
                lo.x = to_tf32(lo.x); lo.y = to_tf32(lo.y);
                hi.x = to_tf32(hi.x); hi.y = to_tf32(hi.y);
            }
            *(float2*)(C + (size_t)m * Cstride + n) = lo;
            *(float2*)(C + (size_t)(m + 8) * Cstride + n) = hi;
        }
    }
}

// ============================================================================
// Pre-pass kernels
// ============================================================================
__global__ __launch_bounds__(256) void round_kernel(
    const float* __restrict__ in, float* __restrict__ out, int n4)
{
    int i = blockIdx.x * 256 + threadIdx.x;
    if (i < n4) {
        float4 v = ((const float4*)in)[i];
        v.x = to_tf32(v.x); v.y = to_tf32(v.y);
        v.z = to_tf32(v.z); v.w = to_tf32(v.w);
        ((float4*)out)[i] = v;
    }
}

// Transpose + tf32-round all weights. z: 0..2=Wq/Wk/Wv, 3=W1, 4=W2.
__global__ __launch_bounds__(256) void transpose_all(
    const float* __restrict__ Wq, const float* __restrict__ Wk, const float* __restrict__ Wv,
    const float* __restrict__ W1, const float* __restrict__ W2,
    float* __restrict__ wqkvT, float* __restrict__ w1T, float* __restrict__ w2T)
{
    __shared__ float t[32][33];
    const int z = blockIdx.z;
    const float* in;
    float* out;
    int R, C;
    if (z < 3)      { in = z == 0 ? Wq : z == 1 ? Wk : Wv; out = wqkvT + (size_t)z * D_MODEL * D_MODEL; R = 512; C = 512; }
    else if (z == 3){ in = W1; out = w1T; R = 512; C = 2048; }
    else            { in = W2; out = w2T; R = 2048; C = 512; }
    const int cb = blockIdx.x * 32, rb = blockIdx.y * 32;
    if (cb >= C || rb >= R) return;
    const int tx = threadIdx.x & 31, ty = threadIdx.x >> 5;
    for (int i = ty; i < 32; i += 8) t[i][tx] = in[(size_t)(rb + i) * C + cb + tx];
    __syncthreads();
    for (int i = ty; i < 32; i += 8) out[(size_t)(cb + i) * R + rb + tx] = to_tf32(t[tx][i]);
}

// Per-batch V transpose: vT[b][d][s] = v[b*TSEQ + s][d] (v already tf32).
__global__ __launch_bounds__(256) void vtrans_kernel(
    const float* __restrict__ v, float* __restrict__ vT)
{
    __shared__ float t[32][33];
    const int b  = blockIdx.z;
    const int sb = blockIdx.x * 32;
    const int db = blockIdx.y * 32;
    const float* in = v + (size_t)b * TSEQ * D_MODEL;
    float* out = vT + (size_t)b * D_MODEL * TSEQ;
    const int tx = threadIdx.x & 31, ty = threadIdx.x >> 5;
    for (int i = ty; i < 32; i += 8) t[i][tx] = in[(size_t)(sb + i) * D_MODEL + db + tx];
    __syncthreads();
    for (int i = ty; i < 32; i += 8) out[(size_t)(db + i) * TSEQ + sb + tx] = t[tx][i];
}

// ---------------------------------------------------------------------------
// FMA-only exp (input <= 0 after max-subtract; clamped).
// ---------------------------------------------------------------------------
__device__ __forceinline__ float fast_exp(float x) {
    x = fmaxf(x, -87.0f);
    float z = x * 1.4426950408889634f;
    float n = rintf(z);
    float t = z - n;
    float p = 1.5403530e-4f;
    p = fmaf(p, t, 1.3333558e-3f);
    p = fmaf(p, t, 9.6181291e-3f);
    p = fmaf(p, t, 5.5504109e-2f);
    p = fmaf(p, t, 2.4022651e-1f);
    p = fmaf(p, t, 6.9314718e-1f);
    p = fmaf(p, t, 1.0f);
    int e = (int)n;
    return p * __int_as_float((e + 127) << 23);
}

// ============================================================================
// Row softmax (in-place, register-resident). tf32-rounded output.
// Zero-fill to next 128 boundary (PV TBM=128, K clamp at m0+128).
// ============================================================================
__global__ __launch_bounds__(256) void softmax_kernel(
    float* __restrict__ S, const float* __restrict__ ds_ptr)
{
    __shared__ float red[8];

    const int t = blockIdx.x;
    const int b = blockIdx.y;
    const int tid = threadIdx.x;
    const int lane = tid & 31;
    const int wid  = tid >> 5;
    float* row = S + ((size_t)b * TSEQ + t) * TSEQ;

    const float ds = *ds_ptr;
    const float scale = rsqrtf((float)D_MODEL);
    const int len = t + 1;
    const int limit = ((t >> 7) + 1) << 7;

    float v[16];
    float mx = -1e30f;
#pragma unroll
    for (int it = 0; it < 16; it++) {
        int s = tid + it * 256;
        float val = -1e30f;
        if (s < len) val = (row[s] - ds * (float)(t - s)) * scale;
        v[it] = val;
        mx = fmaxf(mx, val);
    }
#pragma unroll
    for (int o = 16; o; o >>= 1) mx = fmaxf(mx, __shfl_xor_sync(0xffffffffu, mx, o));
    if (lane == 0) red[wid] = mx;
    __syncthreads();
    float mall = -1e30f;
#pragma unroll
    for (int w = 0; w < 8; w++) mall = fmaxf(mall, red[w]);
    __syncthreads();

    float sum = 0.f;
#pragma unroll
    for (int it = 0; it < 16; it++) {
        int s = tid + it * 256;
        float e = (s < len) ? fast_exp(v[it] - mall) : 0.f;
        v[it] = e;
        sum += e;
    }
#pragma unroll
    for (int o = 16; o; o >>= 1) sum += __shfl_xor_sync(0xffffffffu, sum, o);
    if (lane == 0) red[wid] = sum;
    __syncthreads();
    float sall = 0.f;
#pragma unroll
    for (int w = 0; w < 8; w++) sall += red[w];
    const float inv = 1.0f / sall;

#pragma unroll
    for (int it = 0; it < 16; it++) {
        int s = tid + it * 256;
        if (s < len)        row[s] = to_tf32(v[it] * inv);
        else if (s < limit) row[s] = 0.f;
    }
}

// ============================================================================
// LayerNorm: out = LN(A + R) * gamma + beta.  ROUND rounds to tf32.
// ============================================================================
template <int ROUND>
__global__ __launch_bounds__(128) void ln_kernel(
    const float* __restrict__ A, const float* __restrict__ R,
    const float* __restrict__ gamma, const float* __restrict__ beta,
    float* __restrict__ out)
{
    __shared__ float sh[4];
    const int row = blockIdx.x;
    const int tid = threadIdx.x;
    const size_t base = (size_t)row * D_MODEL + tid * 4;

    float4 a = *(const float4*)(A + base);
    float4 r = *(const float4*)(R + base);
    float x0 = a.x + r.x, x1 = a.y + r.y, x2 = a.z + r.z, x3 = a.w + r.w;

    float s = x0 + x1 + x2 + x3;
    for (int o = 16; o; o >>= 1) s += __shfl_xor_sync(0xffffffffu, s, o);
    if ((tid & 31) == 0) sh[tid >> 5] = s;
    __syncthreads();
    const float mean = (sh[0] + sh[1] + sh[2] + sh[3]) * (1.0f / D_MODEL);
    __syncthreads();

    float d0 = x0 - mean, d1 = x1 - mean, d2 = x2 - mean, d3 = x3 - mean;
    float sq = d0 * d0 + d1 * d1 + d2 * d2 + d3 * d3;
    for (int o = 16; o; o >>= 1) sq += __shfl_xor_sync(0xffffffffu, sq, o);
    if ((tid & 31) == 0) sh[tid >> 5] = sq;
    __syncthreads();
    const float var = (sh[0] + sh[1] + sh[2] + sh[3]) * (1.0f / D_MODEL);
    const float rstd = rsqrtf(var + 1e-5f);

    float4 g  = *(const float4*)(gamma + tid * 4);
    float4 be = *(const float4*)(beta + tid * 4);
    float4 o4;
    o4.x = d0 * rstd * g.x + be.x;
    o4.y = d1 * rstd * g.y + be.y;
    o4.z = d2 * rstd * g.z + be.z;
    o4.w = d3 * rstd * g.w + be.w;
    if (ROUND) {
        o4.x = to_tf32(o4.x); o4.y = to_tf32(o4.y);
        o4.z = to_tf32(o4.z); o4.w = to_tf32(o4.w);
    }
    *(float4*)(out + base) = o4;
}

// ============================================================================
// Host: tensormap construction via driver entry point (no -lcuda needed)
// ============================================================================
typedef CUresult (*PFN_tmapEncode)(
    CUtensorMap*, CUtensorMapDataType, cuuint32_t, void*,
    const cuuint64_t*, const cuuint64_t*, const cuuint32_t*, const cuuint32_t*,
    CUtensorMapInterleave, CUtensorMapSwizzle, CUtensorMapL2promotion,
    CUtensorMapFloatOOBfill);

static void mk2d(PFN_tmapEncode enc, CUtensorMap* m, void* ptr,
                 uint64_t rows, uint64_t cols, uint32_t boxRows)
{
    cuuint64_t dims[2]    = {cols, rows};
    cuuint64_t strides[1] = {cols * 4};
    cuuint32_t box[2]     = {32, boxRows};
    cuuint32_t es[2]      = {1, 1};
    enc(m, CU_TENSOR_MAP_DATA_TYPE_FLOAT32, 2, ptr, dims, strides, box, es,
        CU_TENSOR_MAP_INTERLEAVE_NONE, CU_TENSOR_MAP_SWIZZLE_128B,
        CU_TENSOR_MAP_L2_PROMOTION_L2_128B, CU_TENSOR_MAP_FLOAT_OOB_FILL_NONE);
}

// ============================================================================
// Launch sequence (graph-capturable)
// ============================================================================
extern "C" void kernel_launch(void* const* d_in, const int* in_sizes, int n_in,
                              void* d_out, int out_size)
{
    const float* tokens = (const float*)d_in[0];
    const float* Wq = (const float*)d_in[1];
    const float* bq = (const float*)d_in[2];
    const float* Wk = (const float*)d_in[3];
    const float* bk = (const float*)d_in[4];
    const float* Wv = (const float*)d_in[5];
    const float* bv = (const float*)d_in[6];
    const float* ds = (const float*)d_in[7];
    const float* W1 = (const float*)d_in[8];
    const float* b1 = (const float*)d_in[9];
    const float* W2 = (const float*)d_in[10];
    const float* b2 = (const float*)d_in[11];
    const float* g1 = (const float*)d_in[12];
    const float* be1 = (const float*)d_in[13];
    const float* g2 = (const float*)d_in[14];
    const float* be2 = (const float*)d_in[15];
    float* out = (float*)d_out;

    float *q, *k, *v, *vT, *attn, *x, *y, *h, *s, *tokr, *wqkvT, *w1T, *w2T;
    cudaGetSymbolAddress((void**)&q, g_q);
    cudaGetSymbolAddress((void**)&k, g_k);
    cudaGetSymbolAddress((void**)&v, g_v);
    cudaGetSymbolAddress((void**)&vT, g_vT);
    cudaGetSymbolAddress((void**)&attn, g_attn);
    cudaGetSymbolAddress((void**)&x, g_x);
    cudaGetSymbolAddress((void**)&y, g_y);
    cudaGetSymbolAddress((void**)&h, g_h);
    cudaGetSymbolAddress((void**)&s, g_s);
    cudaGetSymbolAddress((void**)&tokr, g_tokr);
    cudaGetSymbolAddress((void**)&wqkvT, g_wqkvT);
    cudaGetSymbolAddress((void**)&w1T, g_w1T);
    cudaGetSymbolAddress((void**)&w2T, g_w2T);

    PFN_tmapEncode enc = nullptr;
    {
        void* p = nullptr;
        cudaDriverEntryPointQueryResult st;
        cudaGetDriverEntryPoint("cuTensorMapEncodeTiled", &p, cudaEnableDefault, &st);
        enc = (PFN_tmapEncode)p;
    }

    CUtensorMap tmTok, tmWqkv, tmQ, tmK, tmX, tmW1, tmH, tmW2, tmP, tmV;
    mk2d(enc, &tmTok,  tokr,  NTOK,           D_MODEL, 128);
    mk2d(enc, &tmWqkv, wqkvT, 3 * D_MODEL,    D_MODEL, 128);
    mk2d(enc, &tmQ,    q,     NTOK,           D_MODEL, 128);
    mk2d(enc, &tmK,    k,     NTOK,           D_MODEL, 128);
    mk2d(enc, &tmX,    x,     NTOK,           D_MODEL, 128);
    mk2d(enc, &tmW1,   w1T,   HDIM,           D_MODEL, 128);
    mk2d(enc, &tmH,    h,     NTOK,           HDIM,    128);
    mk2d(enc, &tmW2,   w2T,   D_MODEL,        HDIM,    128);
    mk2d(enc, &tmP,    s,     (uint64_t)NB * TSEQ, TSEQ, 128);
    mk2d(enc, &tmV,    vT,    (uint64_t)NB * D_MODEL, TSEQ, 128);

    cudaFuncSetAttribute(gemm_tma<0, 1, 0, 1, 0>, cudaFuncAttributeMaxDynamicSharedMemorySize, TSMEM_BYTES);
    cudaFuncSetAttribute(gemm_tma<0, 0, 1, 0, 0>, cudaFuncAttributeMaxDynamicSharedMemorySize, TSMEM_BYTES);
    cudaFuncSetAttribute(gemm_tma<0, 0, 0, 0, 1>, cudaFuncAttributeMaxDynamicSharedMemorySize, TSMEM_BYTES);
    cudaFuncSetAttribute(gemm_tma<1, 1, 0, 0, 0>, cudaFuncAttributeMaxDynamicSharedMemorySize, TSMEM_BYTES);
    cudaFuncSetAttribute(gemm_tma<0, 0, 0, 0, 0>, cudaFuncAttributeMaxDynamicSharedMemorySize, TSMEM_BYTES);

    // 0: round tokens to tf32
    round_kernel<<<(NTOK * D_MODEL / 4 + 255) / 256, 256>>>(tokens, tokr, NTOK * D_MODEL / 4);

    // 1: transpose+round all weights
    transpose_all<<<dim3(64, 64, 5), 256>>>(Wq, Wk, Wv, W1, W2, wqkvT, w1T, w2T);

    // 2: QKV (TMA): C_z = tokr @ Wz^T + bz, tf32-rounded
    gemm_tma<0, 1, 0, 1, 0><<<dim3(D_MODEL / TBN, NTOK / TBM, 3), 128, TSMEM_BYTES>>>(
        tmTok, tmWqkv, bq, bk, bv, q, k, v, D_MODEL, D_MODEL, 0, D_MODEL, 0);

    // 2b: vT[b][d][s] = v
    vtrans_kernel<<<dim3(TSEQ / 32, D_MODEL / 32, NB), 256>>>(v, vT);

    // 3: scores (TMA, causal-skip): S = Q @ K^T per batch
    gemm_tma<0, 0, 1, 0, 0><<<dim3(TSEQ / TBN, TSEQ / TBM, NB), 128, TSMEM_BYTES>>>(
        tmQ, tmK, nullptr, nullptr, nullptr, s, nullptr, nullptr,
        TSEQ, D_MODEL, TSEQ, TSEQ, (long)TSEQ * TSEQ);

    // 4: softmax (zero-fill to 128 boundary)
    softmax_kernel<<<dim3(TSEQ, NB), 256>>>(s, ds);

    // 5: PV (TMA, K clamped to m0+128): attn = P @ vT^T
    gemm_tma<0, 0, 0, 0, 1><<<dim3(D_MODEL / TBN, TSEQ / TBM, NB), 128, TSMEM_BYTES>>>(
        tmP, tmV, nullptr, nullptr, nullptr, attn, nullptr, nullptr,
        D_MODEL, TSEQ, TSEQ, D_MODEL, (long)TSEQ * D_MODEL);

    // 6: x = LN(tokens + attn), tf32-rounded
    ln_kernel<1><<<NTOK, 128>>>(tokens, attn, g1, be1, x);

    // 7: FFN1 (TMA): h = relu(x @ W1^T' + b1), tf32-rounded
    gemm_tma<1, 1, 0, 0, 0><<<dim3(HDIM / TBN, NTOK / TBM, 1), 128, TSMEM_BYTES>>>(
        tmX, tmW1, b1, nullptr, nullptr, h, nullptr, nullptr,
        HDIM, D_MODEL, 0, 0, 0);

    // 8: FFN2 (TMA): y = h @ W2^T' + b2
    gemm_tma<0, 0, 0, 0, 0><<<dim3(D_MODEL / TBN, NTOK / TBM, 1), 128, TSMEM_BYTES>>>(
        tmH, tmW2, b2, nullptr, nullptr, y, nullptr, nullptr,
        D_MODEL, HDIM, 0, 0, 0);

    // 9: z = LN(y + x)
    ln_kernel<0><<<NTOK, 128>>>(y, x, g2, be2, out);
}

// round 15
// speedup vs baseline: 1.2240x; 1.0072x over previous
#include <cuda_runtime.h>
#include <cuda.h>
#include <math.h>
#include <stdint.h>

// Problem constants
#define D_MODEL 512
#define HDIM    2048
#define TSEQ    4096
#define NB      2
#define NTOK    (NB * TSEQ)  // 8192

// ---- TMA kernel config: 128x128 tile, 128 threads, 2 CTAs/SM ----
#define TBM 128
#define TBN 128
#define TBK 32
#define A_STAGE_B 16384            // 128 rows * 128 B
#define B_STAGE_B 16384
#define STAGE_B   (A_STAGE_B + B_STAGE_B)   // 32768
#define NST 3
#define TSMEM_BYTES (NST * STAGE_B + 128)   // 98432

// -------- static scratch (allocation-free per harness rules) --------
__device__ float g_q[(size_t)NTOK * D_MODEL];
__device__ float g_k[(size_t)NTOK * D_MODEL];
__device__ float g_vT[(size_t)NB * D_MODEL * TSEQ];   // [b][d][s]
__device__ float g_attn[(size_t)NTOK * D_MODEL];
__device__ float g_x[(size_t)NTOK * D_MODEL];
__device__ float g_y[(size_t)NTOK * D_MODEL];
__device__ float g_h[(size_t)NTOK * HDIM];
__device__ float g_s[(size_t)NB * TSEQ * TSEQ];
__device__ float g_tokr[(size_t)NTOK * D_MODEL];
__device__ float g_wqkvT[(size_t)3 * D_MODEL * D_MODEL];
__device__ float g_w1T[(size_t)HDIM * D_MODEL];
__device__ float g_w2T[(size_t)D_MODEL * HDIM];

// ---------------------------------------------------------------------------
// helpers
// ---------------------------------------------------------------------------
__device__ __forceinline__ float to_tf32(float x) {
    uint32_t u;
    asm("cvt.rna.tf32.f32 %0, %1;" : "=r"(u) : "f"(x));
    return __uint_as_float(u);
}

__device__ __forceinline__ void mma_tf32(float c[4], const float a[4], const float b[2]) {
    asm volatile(
        "mma.sync.aligned.m16n8k8.row.col.f32.tf32.tf32.f32 "
        "{%0,%1,%2,%3}, {%4,%5,%6,%7}, {%8,%9}, {%0,%1,%2,%3};"
        : "+f"(c[0]), "+f"(c[1]), "+f"(c[2]), "+f"(c[3])
        : "r"(__float_as_uint(a[0])), "r"(__float_as_uint(a[1])),
          "r"(__float_as_uint(a[2])), "r"(__float_as_uint(a[3])),
          "r"(__float_as_uint(b[0])), "r"(__float_as_uint(b[1])));
}

__device__ __forceinline__ uint32_t smem_u32(const void* p) {
    return (uint32_t)__cvta_generic_to_shared(p);
}

// ---- mbarrier / TMA primitives ----
__device__ __forceinline__ void mbar_init(uint32_t a, uint32_t cnt) {
    asm volatile("mbarrier.init.shared.b64 [%0], %1;" :: "r"(a), "r"(cnt) : "memory");
}
__device__ __forceinline__ void mbar_expect(uint32_t a, uint32_t tx) {
    asm volatile("mbarrier.arrive.expect_tx.shared.b64 _, [%0], %1;" :: "r"(a), "r"(tx) : "memory");
}
__device__ __forceinline__ void mbar_wait(uint32_t a, int parity) {
    asm volatile(
        "{\n\t"
        ".reg .pred P1;\n\t"
        "WAIT_LOOP_%=:\n\t"
        "mbarrier.try_wait.parity.acquire.cta.shared::cta.b64 P1, [%0], %1, 0x989680;\n\t"
        "@P1 bra.uni WAIT_DONE_%=;\n\t"
        "bra.uni WAIT_LOOP_%=;\n\t"
        "WAIT_DONE_%=:\n\t"
        "}"
        :: "r"(a), "r"(parity) : "memory");
}
__device__ __forceinline__ void tma2d(uint32_t dst, const void* map, int cx, int cy, uint32_t bar) {
    asm volatile(
        "cp.async.bulk.tensor.2d.shared::cta.global.tile.mbarrier::complete_tx::bytes "
        "[%0], [%1, {%2, %3}], [%4];"
        :: "r"(dst), "l"(map), "r"(cx), "r"(cy), "r"(bar) : "memory");
}

// SW128-swizzled fp32 element in a [rows][32] tile with 128B rows
__device__ __forceinline__ float SWF(const char* base, int row, int col) {
    int off = row * 128 + col * 4;
    off ^= (off >> 3) & 0x70;
    return *(const float*)(base + off);
}

// ============================================================================
// TMA-fed tf32 GEMM: C[128 x 128] per CTA, 128 threads, 4 warps of 64x64.
// 3-stage pipeline, prefetch issued BEFORE compute. 2 CTAs/SM (96KB smem).
// A map [Mtot,K] box(32,128); B map [Ntot,K] box(32,128); C = A @ B^T.
//   CAUSAL=1: skip score tiles fully above diagonal (bx > by);
//   MULTI=1:  blockIdx.z selects out/bias (QKV); z==2 (V) stores TRANSPOSED
//             into o2 = vT[b][d][s] (b = m>>12, s = m&4095, d = n);
//   else out = o0 + z*ozs;
//   KCAU=1:   K clamped to m0+TBM (causal P@V).
// ============================================================================
template <int RELU, int ROUND, int CAUSAL, int MULTI, int KCAU>
__global__ __launch_bounds__(128, 2) void gemm_tma(
    const __grid_constant__ CUtensorMap tmA,
    const __grid_constant__ CUtensorMap tmB,
    const float* __restrict__ b0, const float* __restrict__ b1, const float* __restrict__ b2,
    float* __restrict__ o0, float* __restrict__ o1, float* __restrict__ o2,
    int Cstride, int K, int za, int zb, long ozs)
{
    if (CAUSAL && (int)blockIdx.x > (int)blockIdx.y) return;

    extern __shared__ __align__(1024) char smem[];
    const int tid = threadIdx.x;
    const int z   = blockIdx.z;
    const int m0  = blockIdx.y * TBM;
    const int n0  = blockIdx.x * TBN;
    const int ya  = m0 + z * za;
    const int yb  = n0 + z * zb;
    const uint32_t sbase = smem_u32(smem);
    const uint32_t barb = sbase + NST * STAGE_B;
    const int Keff = KCAU ? min(K, m0 + TBM) : K;
    const int NS = Keff / TBK;

    if (tid == 0) {
        mbar_init(barb + 0, 1);
        mbar_init(barb + 8, 1);
        mbar_init(barb + 16, 1);
    }
    __syncthreads();
    if (tid == 0) {
        mbar_expect(barb + 0, STAGE_B);
        tma2d(sbase, &tmA, 0, ya, barb + 0);
        tma2d(sbase + A_STAGE_B, &tmB, 0, yb, barb + 0);
        mbar_expect(barb + 8, STAGE_B);
        tma2d(sbase + STAGE_B, &tmA, TBK, ya, barb + 8);
        tma2d(sbase + STAGE_B + A_STAGE_B, &tmB, TBK, yb, barb + 8);
    }

    const int lane = tid & 31;
    const int gid  = lane >> 2;
    const int tg   = lane & 3;
    const int warp = tid >> 5;          // 0..3
    const int mw   = (warp >> 1) * 64;
    const int nw   = (warp & 1) * 64;

    float acc[4][8][4] = {};

    for (int s = 0; s < NS; s++) {
        const int slot = s % NST;
        mbar_wait(barb + 8 * slot, (s / NST) & 1);
        __syncthreads();  // all warps finished stage s-1 -> slot (s+2)%NST reusable
        if (tid == 0 && s + 2 < NS) {
            const int ps = (s + 2) % NST;
            mbar_expect(barb + 8 * ps, STAGE_B);
            tma2d(sbase + ps * STAGE_B, &tmA, (s + 2) * TBK, ya, barb + 8 * ps);
            tma2d(sbase + ps * STAGE_B + A_STAGE_B, &tmB, (s + 2) * TBK, yb, barb + 8 * ps);
        }

        const char* As = smem + slot * STAGE_B;
        const char* Bs = As + A_STAGE_B;

#pragma unroll
        for (int ks = 0; ks < 4; ks++) {
            const int kk = ks * 8;
            float a[4][4];
#pragma unroll
            for (int i = 0; i < 4; i++) {
                int r = mw + i * 16 + gid;
                a[i][0] = SWF(As, r,     kk + tg);
                a[i][1] = SWF(As, r + 8, kk + tg);
                a[i][2] = SWF(As, r,     kk + tg + 4);
                a[i][3] = SWF(As, r + 8, kk + tg + 4);
            }
            float bb[8][2];
#pragma unroll
            for (int j = 0; j < 8; j++) {
                int r = nw + j * 8 + gid;
                bb[j][0] = SWF(Bs, r, kk + tg);
                bb[j][1] = SWF(Bs, r, kk + tg + 4);
            }
#pragma unroll
            for (int i = 0; i < 4; i++)
#pragma unroll
                for (int j = 0; j < 8; j++) mma_tf32(acc[i][j], a[i], bb[j]);
        }
    }

    // ---- epilogue ----
    float* C;
    const float* bias;
    if (MULTI) {
        C    = (z == 0) ? o0 : (z == 1) ? o1 : o2;
        bias = (z == 0) ? b0 : (z == 1) ? b1 : b2;
    } else {
        C    = o0 + (size_t)z * ozs;
        bias = b0;
    }
#pragma unroll
    for (int i = 0; i < 4; i++) {
        int m = m0 + mw + i * 16 + gid;
#pragma unroll
        for (int j = 0; j < 8; j++) {
            int n = n0 + nw + j * 8 + tg * 2;
            float2 lo = make_float2(acc[i][j][0], acc[i][j][1]);
            float2 hi = make_float2(acc[i][j][2], acc[i][j][3]);
            if (bias) {
                float u0 = bias[n], u1 = bias[n + 1];
                lo.x += u0; lo.y += u1; hi.x += u0; hi.y += u1;
            }
            if (RELU) {
                lo.x = fmaxf(lo.x, 0.f); lo.y = fmaxf(lo.y, 0.f);
                hi.x = fmaxf(hi.x, 0.f); hi.y = fmaxf(hi.y, 0.f);
            }
            if (ROUND) {
                lo.x = to_tf32(lo.x); lo.y = to_tf32(lo.y);
                hi.x = to_tf32(hi.x); hi.y = to_tf32(hi.y);
            }
            if (MULTI && z == 2) {
                // transposed V store: vT[(b*512 + n)*4096 + s], b=m>>12, s=m&4095
                int b_  = m >> 12;
                int s0  = m & 4095;
                size_t base = ((size_t)(b_ << 9) + n) * 4096;
                C[base + s0]            = lo.x;
                C[base + 4096 + s0]     = lo.y;
                C[base + s0 + 8]        = hi.x;
                C[base + 4096 + s0 + 8] = hi.y;
            } else {
                *(float2*)(C + (size_t)m * Cstride + n) = lo;
                *(float2*)(C + (size_t)(m + 8) * Cstride + n) = hi;
            }
        }
    }
}

// ============================================================================
// Pre-pass kernels
// ============================================================================
__global__ __launch_bounds__(256) void round_kernel(
    const float* __restrict__ in, float* __restrict__ out, int n4)
{
    int i = blockIdx.x * 256 + threadIdx.x;
    if (i < n4) {
        float4 v = ((const float4*)in)[i];
        v.x = to_tf32(v.x); v.y = to_tf32(v.y);
        v.z = to_tf32(v.z); v.w = to_tf32(v.w);
        ((float4*)out)[i] = v;
    }
}

// Transpose + tf32-round all weights. z: 0..2=Wq/Wk/Wv, 3=W1, 4=W2.
__global__ __launch_bounds__(256) void transpose_all(
    const float* __restrict__ Wq, const float* __restrict__ Wk, const float* __restrict__ Wv,
    const float* __restrict__ W1, const float* __restrict__ W2,
    float* __restrict__ wqkvT, float* __restrict__ w1T, float* __restrict__ w2T)
{
    __shared__ float t[32][33];
    const int z = blockIdx.z;
    const float* in;
    float* out;
    int R, C;
    if (z < 3)      { in = z == 0 ? Wq : z == 1 ? Wk : Wv; out = wqkvT + (size_t)z * D_MODEL * D_MODEL; R = 512; C = 512; }
    else if (z == 3){ in = W1; out = w1T; R = 512; C = 2048; }
    else            { in = W2; out = w2T; R = 2048; C = 512; }
    const int cb = blockIdx.x * 32, rb = blockIdx.y * 32;
    if (cb >= C || rb >= R) return;
    const int tx = threadIdx.x & 31, ty = threadIdx.x >> 5;
    for (int i = ty; i < 32; i += 8) t[i][tx] = in[(size_t)(rb + i) * C + cb + tx];
    __syncthreads();
    for (int i = ty; i < 32; i += 8) out[(size_t)(cb + i) * R + rb + tx] = to_tf32(t[tx][i]);
}

// ---------------------------------------------------------------------------
// FMA-only exp (input <= 0 after max-subtract; clamped).
// ---------------------------------------------------------------------------
__device__ __forceinline__ float fast_exp(float x) {
    x = fmaxf(x, -87.0f);
    float z = x * 1.4426950408889634f;
    float n = rintf(z);
    float t = z - n;
    float p = 1.5403530e-4f;
    p = fmaf(p, t, 1.3333558e-3f);
    p = fmaf(p, t, 9.6181291e-3f);
    p = fmaf(p, t, 5.5504109e-2f);
    p = fmaf(p, t, 2.4022651e-1f);
    p = fmaf(p, t, 6.9314718e-1f);
    p = fmaf(p, t, 1.0f);
    int e = (int)n;
    return p * __int_as_float((e + 127) << 23);
}

// ============================================================================
// Row softmax (in-place, register-resident). tf32-rounded output.
// Zero-fill to next 128 boundary (PV TBM=128, K clamp at m0+128).
// ============================================================================
__global__ __launch_bounds__(256) void softmax_kernel(
    float* __restrict__ S, const float* __restrict__ ds_ptr)
{
    __shared__ float red[8];

    const int t = blockIdx.x;
    const int b = blockIdx.y;
    const int tid = threadIdx.x;
    const int lane = tid & 31;
    const int wid  = tid >> 5;
    float* row = S + ((size_t)b * TSEQ + t) * TSEQ;

    const float ds = *ds_ptr;
    const float scale = rsqrtf((float)D_MODEL);
    const int len = t + 1;
    const int limit = ((t >> 7) + 1) << 7;

    float v[16];
    float mx = -1e30f;
#pragma unroll
    for (int it = 0; it < 16; it++) {
        int s = tid + it * 256;
        float val = -1e30f;
        if (s < len) val = (row[s] - ds * (float)(t - s)) * scale;
        v[it] = val;
        mx = fmaxf(mx, val);
    }
#pragma unroll
    for (int o = 16; o; o >>= 1) mx = fmaxf(mx, __shfl_xor_sync(0xffffffffu, mx, o));
    if (lane == 0) red[wid] = mx;
    __syncthreads();
    float mall = -1e30f;
#pragma unroll
    for (int w = 0; w < 8; w++) mall = fmaxf(mall, red[w]);
    __syncthreads();

    float sum = 0.f;
#pragma unroll
    for (int it = 0; it < 16; it++) {
        int s = tid + it * 256;
        float e = (s < len) ? fast_exp(v[it] - mall) : 0.f;
        v[it] = e;
        sum += e;
    }
#pragma unroll
    for (int o = 16; o; o >>= 1) sum += __shfl_xor_sync(0xffffffffu, sum, o);
    if (lane == 0) red[wid] = sum;
    __syncthreads();
    float sall = 0.f;
#pragma unroll
    for (int w = 0; w < 8; w++) sall += red[w];
    const float inv = 1.0f / sall;

#pragma unroll
    for (int it = 0; it < 16; it++) {
        int s = tid + it * 256;
        if (s < len)        row[s] = to_tf32(v[it] * inv);
        else if (s < limit) row[s] = 0.f;
    }
}

// ============================================================================
// LayerNorm: out = LN(A + R) * gamma + beta.  ROUND rounds to tf32.
// ============================================================================
template <int ROUND>
__global__ __launch_bounds__(128) void ln_kernel(
    const float* __restrict__ A, const float* __restrict__ R,
    const float* __restrict__ gamma, const float* __restrict__ beta,
    float* __restrict__ out)
{
    __shared__ float sh[4];
    const int row = blockIdx.x;
    const int tid = threadIdx.x;
    const size_t base = (size_t)row * D_MODEL + tid * 4;

    float4 a = *(const float4*)(A + base);
    float4 r = *(const float4*)(R + base);
    float x0 = a.x + r.x, x1 = a.y + r.y, x2 = a.z + r.z, x3 = a.w + r.w;

    float s = x0 + x1 + x2 + x3;
    for (int o = 16; o; o >>= 1) s += __shfl_xor_sync(0xffffffffu, s, o);
    if ((tid & 31) == 0) sh[tid >> 5] = s;
    __syncthreads();
    const float mean = (sh[0] + sh[1] + sh[2] + sh[3]) * (1.0f / D_MODEL);
    __syncthreads();

    float d0 = x0 - mean, d1 = x1 - mean, d2 = x2 - mean, d3 = x3 - mean;
    float sq = d0 * d0 + d1 * d1 + d2 * d2 + d3 * d3;
    for (int o = 16; o; o >>= 1) sq += __shfl_xor_sync(0xffffffffu, sq, o);
    if ((tid & 31) == 0) sh[tid >> 5] = sq;
    __syncthreads();
    const float var = (sh[0] + sh[1] + sh[2] + sh[3]) * (1.0f / D_MODEL);
    const float rstd = rsqrtf(var + 1e-5f);

    float4 g  = *(const float4*)(gamma + tid * 4);
    float4 be = *(const float4*)(beta + tid * 4);
    float4 o4;
    o4.x = d0 * rstd * g.x + be.x;
    o4.y = d1 * rstd * g.y + be.y;
    o4.z = d2 * rstd * g.z + be.z;
    o4.w = d3 * rstd * g.w + be.w;
    if (ROUND) {
        o4.x = to_tf32(o4.x); o4.y = to_tf32(o4.y);
        o4.z = to_tf32(o4.z); o4.w = to_tf32(o4.w);
    }
    *(float4*)(out + base) = o4;
}

// ============================================================================
// Host: tensormap construction via driver entry point (no -lcuda needed)
// ============================================================================
typedef CUresult (*PFN_tmapEncode)(
    CUtensorMap*, CUtensorMapDataType, cuuint32_t, void*,
    const cuuint64_t*, const cuuint64_t*, const cuuint32_t*, const cuuint32_t*,
    CUtensorMapInterleave, CUtensorMapSwizzle, CUtensorMapL2promotion,
    CUtensorMapFloatOOBfill);

static void mk2d(PFN_tmapEncode enc, CUtensorMap* m, void* ptr,
                 uint64_t rows, uint64_t cols, uint32_t boxRows)
{
    cuuint64_t dims[2]    = {cols, rows};
    cuuint64_t strides[1] = {cols * 4};
    cuuint32_t box[2]     = {32, boxRows};
    cuuint32_t es[2]      = {1, 1};
    enc(m, CU_TENSOR_MAP_DATA_TYPE_FLOAT32, 2, ptr, dims, strides, box, es,
        CU_TENSOR_MAP_INTERLEAVE_NONE, CU_TENSOR_MAP_SWIZZLE_128B,
        CU_TENSOR_MAP_L2_PROMOTION_L2_128B, CU_TENSOR_MAP_FLOAT_OOB_FILL_NONE);
}

// ============================================================================
// Launch sequence (graph-capturable)
// ============================================================================
extern "C" void kernel_launch(void* const* d_in, const int* in_sizes, int n_in,
                              void* d_out, int out_size)
{
    const float* tokens = (const float*)d_in[0];
    const float* Wq = (const float*)d_in[1];
    const float* bq = (const float*)d_in[2];
    const float* Wk = (const float*)d_in[3];
    const float* bk = (const float*)d_in[4];
    const float* Wv = (const float*)d_in[5];
    const float* bv = (const float*)d_in[6];
    const float* ds = (const float*)d_in[7];
    const float* W1 = (const float*)d_in[8];
    const float* b1 = (const float*)d_in[9];
    const float* W2 = (const float*)d_in[10];
    const float* b2 = (const float*)d_in[11];
    const float* g1 = (const float*)d_in[12];
    const float* be1 = (const float*)d_in[13];
    const float* g2 = (const float*)d_in[14];
    const float* be2 = (const float*)d_in[15];
    float* out = (float*)d_out;

    float *q, *k, *vT, *attn, *x, *y, *h, *s, *tokr, *wqkvT, *w1T, *w2T;
    cudaGetSymbolAddress((void**)&q, g_q);
    cudaGetSymbolAddress((void**)&k, g_k);
    cudaGetSymbolAddress((void**)&vT, g_vT);
    cudaGetSymbolAddress((void**)&attn, g_attn);
    cudaGetSymbolAddress((void**)&x, g_x);
    cudaGetSymbolAddress((void**)&y, g_y);
    cudaGetSymbolAddress((void**)&h, g_h);
    cudaGetSymbolAddress((void**)&s, g_s);
    cudaGetSymbolAddress((void**)&tokr, g_tokr);
    cudaGetSymbolAddress((void**)&wqkvT, g_wqkvT);
    cudaGetSymbolAddress((void**)&w1T, g_w1T);
    cudaGetSymbolAddress((void**)&w2T, g_w2T);

    PFN_tmapEncode enc = nullptr;
    {
        void* p = nullptr;
        cudaDriverEntryPointQueryResult st;
        cudaGetDriverEntryPoint("cuTensorMapEncodeTiled", &p, cudaEnableDefault, &st);
        enc = (PFN_tmapEncode)p;
    }

    CUtensorMap tmTok, tmWqkv, tmQ, tmK, tmX, tmW1, tmH, tmW2, tmP, tmV;
    mk2d(enc, &tmTok,  tokr,  NTOK,           D_MODEL, 128);
    mk2d(enc, &tmWqkv, wqkvT, 3 * D_MODEL,    D_MODEL, 128);
    mk2d(enc, &tmQ,    q,     NTOK,           D_MODEL, 128);
    mk2d(enc, &tmK,    k,     NTOK,           D_MODEL, 128);
    mk2d(enc, &tmX,    x,     NTOK,           D_MODEL, 128);
    mk2d(enc, &tmW1,   w1T,   HDIM,           D_MODEL, 128);
    mk2d(enc, &tmH,    h,     NTOK,           HDIM,    128);
    mk2d(enc, &tmW2,   w2T,   D_MODEL,        HDIM,    128);
    mk2d(enc, &tmP,    s,     (uint64_t)NB * TSEQ, TSEQ, 128);
    mk2d(enc, &tmV,    vT,    (uint64_t)NB * D_MODEL, TSEQ, 128);

    cudaFuncSetAttribute(gemm_tma<0, 1, 0, 1, 0>, cudaFuncAttributeMaxDynamicSharedMemorySize, TSMEM_BYTES);
    cudaFuncSetAttribute(gemm_tma<0, 0, 1, 0, 0>, cudaFuncAttributeMaxDynamicSharedMemorySize, TSMEM_BYTES);
    cudaFuncSetAttribute(gemm_tma<0, 0, 0, 0, 1>, cudaFuncAttributeMaxDynamicSharedMemorySize, TSMEM_BYTES);
    cudaFuncSetAttribute(gemm_tma<1, 1, 0, 0, 0>, cudaFuncAttributeMaxDynamicSharedMemorySize, TSMEM_BYTES);
    cudaFuncSetAttribute(gemm_tma<0, 0, 0, 0, 0>, cudaFuncAttributeMaxDynamicSharedMemorySize, TSMEM_BYTES);

    // 0: round tokens to tf32
    round_kernel<<<(NTOK * D_MODEL / 4 + 255) / 256, 256>>>(tokens, tokr, NTOK * D_MODEL / 4);

    // 1: transpose+round all weights
    transpose_all<<<dim3(64, 64, 5), 256>>>(Wq, Wk, Wv, W1, W2, wqkvT, w1T, w2T);

    // 2: QKV (TMA): q,k row-major; V written TRANSPOSED into vT (z==2 path)
    gemm_tma<0, 1, 0, 1, 0><<<dim3(D_MODEL / TBN, NTOK / TBM, 3), 128, TSMEM_BYTES>>>(
        tmTok, tmWqkv, bq, bk, bv, q, k, vT, D_MODEL, D_MODEL, 0, D_MODEL, 0);

    // 3: scores (TMA, causal-skip): S = Q @ K^T per batch
    gemm_tma<0, 0, 1, 0, 0><<<dim3(TSEQ / TBN, TSEQ / TBM, NB), 128, TSMEM_BYTES>>>(
        tmQ, tmK, nullptr, nullptr, nullptr, s, nullptr, nullptr,
        TSEQ, D_MODEL, TSEQ, TSEQ, (long)TSEQ * TSEQ);

    // 4: softmax (zero-fill to 128 boundary)
    softmax_kernel<<<dim3(TSEQ, NB), 256>>>(s, ds);

    // 5: PV (TMA, K clamped to m0+128): attn = P @ vT^T
    gemm_tma<0, 0, 0, 0, 1><<<dim3(D_MODEL / TBN, TSEQ / TBM, NB), 128, TSMEM_BYTES>>>(
        tmP, tmV, nullptr, nullptr, nullptr, attn, nullptr, nullptr,
        D_MODEL, TSEQ, TSEQ, D_MODEL, (long)TSEQ * D_MODEL);

    // 6: x = LN(tokens + attn), tf32-rounded
    ln_kernel<1><<<NTOK, 128>>>(tokens, attn, g1, be1, x);

    // 7: FFN1 (TMA): h = relu(x @ W1^T' + b1), tf32-rounded
    gemm_tma<1, 1, 0, 0, 0><<<dim3(HDIM / TBN, NTOK / TBM, 1), 128, TSMEM_BYTES>>>(
        tmX, tmW1, b1, nullptr, nullptr, h, nullptr, nullptr,
        HDIM, D_MODEL, 0, 0, 0);

    // 8: FFN2 (TMA): y = h @ W2^T' + b2
    gemm_tma<0, 0, 0, 0, 0><<<dim3(D_MODEL / TBN, NTOK / TBM, 1), 128, TSMEM_BYTES>>>(
        tmH, tmW2, b2, nullptr, nullptr, y, nullptr, nullptr,
        D_MODEL, HDIM, 0, 0, 0);

    // 9: z = LN(y + x)
    ln_kernel<0><<<NTOK, 128>>>(y, x, g2, be2, out);
}